// round 12
// baseline (speedup 1.0000x reference)
#include <cuda_runtime.h>
#include <cuda_fp16.h>
#include <cstdint>

// ---------------------------------------------------------------------------
// Problem constants
// ---------------------------------------------------------------------------
#define B_   2
#define S_   2048
#define DM_  768
#define NQK_ 16
#define DQK_ 16
#define NOV_ 256
#define VKV_ 16
#define SK_  (S_ + VKV_)     // 2064 keys = 16 + 16*128 (exact)
#define BS_  (B_ * S_)       // 4096 rows

// ---------------------------------------------------------------------------
// Device scratch
// ---------------------------------------------------------------------------
__device__ __half g_Ah  [BS_ * DM_];
__device__ __half g_Wh1 [DM_ * DM_];
__device__ __half g_Wh2 [DM_ * NOV_];
__device__ float  g_rot [S_ * 16];                  // [s][0..7]=sin, [8..15]=cos
__device__ __half g_Qh  [B_ * NQK_ * S_  * DQK_];
__device__ __half g_Kh  [B_ * NQK_ * SK_ * DQK_];
__device__ __half g_Vh  [B_ * NQK_ * SK_ * DQK_];
__device__ __half g_Zh  [BS_ * NOV_];

// ---------------------------------------------------------------------------
// helpers
// ---------------------------------------------------------------------------
__device__ __forceinline__ uint32_t smem_u32(const void* p) {
    return (uint32_t)__cvta_generic_to_shared(p);
}
__device__ __forceinline__ void cp16(uint32_t s, const void* g) {
    asm volatile("cp.async.cg.shared.global [%0], [%1], 16;" :: "r"(s), "l"(g));
}
__device__ __forceinline__ float ex2f(float x) {
    float y; asm("ex2.approx.ftz.f32 %0, %1;" : "=f"(y) : "f"(x)); return y;
}
__device__ __forceinline__ uint32_t ex2h2(float lo, float hi) {
    uint32_t h, r;
    asm("cvt.rn.f16x2.f32 %0, %1, %2;" : "=r"(h) : "f"(hi), "f"(lo));
    asm("ex2.approx.f16x2 %0, %1;" : "=r"(r) : "r"(h));
    return r;
}
__device__ __forceinline__ void ldm4(uint32_t& r0, uint32_t& r1, uint32_t& r2, uint32_t& r3, uint32_t addr) {
    asm volatile("ldmatrix.sync.aligned.m8n8.x4.shared.b16 {%0,%1,%2,%3}, [%4];"
                 : "=r"(r0), "=r"(r1), "=r"(r2), "=r"(r3) : "r"(addr));
}
__device__ __forceinline__ void ldm4t(uint32_t& r0, uint32_t& r1, uint32_t& r2, uint32_t& r3, uint32_t addr) {
    asm volatile("ldmatrix.sync.aligned.m8n8.x4.trans.shared.b16 {%0,%1,%2,%3}, [%4];"
                 : "=r"(r0), "=r"(r1), "=r"(r2), "=r"(r3) : "r"(addr));
}
__device__ __forceinline__ void mma16816(float* d, const uint32_t* a, const uint32_t* b) {
    asm volatile("mma.sync.aligned.m16n8k16.row.col.f32.f16.f16.f32 "
                 "{%0,%1,%2,%3},{%4,%5,%6,%7},{%8,%9},{%0,%1,%2,%3};"
                 : "+f"(d[0]), "+f"(d[1]), "+f"(d[2]), "+f"(d[3])
                 : "r"(a[0]), "r"(a[1]), "r"(a[2]), "r"(a[3]), "r"(b[0]), "r"(b[1]));
}
__device__ __forceinline__ uint32_t packh2(float x, float y) {
    __half2 h = __floats2half2_rn(x, y);
    return *(uint32_t*)&h;
}

#define QSCALE 0.36067376022224085f   // 0.25 * log2(e)

// ---------------------------------------------------------------------------
// 1) Fused prep (unchanged)
// ---------------------------------------------------------------------------
#define PREP_TQK0 0
#define PREP_V0   384
#define PREP_W20  1152
#define PREP_CV0  1344
#define PREP_RT0  4416
#define PREP_VV0  4480
#define PREP_BLKS 4512

__global__ void prep_kernel(const float* __restrict__ WQ,
                            const float* __restrict__ WK,
                            const float* __restrict__ WV,
                            const float* __restrict__ WO,
                            const float* __restrict__ resid,
                            const float* __restrict__ vk,
                            const float* __restrict__ vv)
{
    __shared__ float sm[64 * 17];
    const int blk = blockIdx.x;
    const int t = threadIdx.x;

    if (blk < PREP_V0) {
        int rem = blk, mat = rem / 192; rem %= 192;
        int h = rem / 12, d0 = (rem % 12) * 64;
        const float* W = mat ? WK : WQ;
        {
            int row = t >> 2, part = t & 3;
            float4 v = *(const float4*)&W[((size_t)h * DM_ + d0 + row) * DQK_ + part * 4];
            sm[row * 17 + part * 4 + 0] = v.x;
            sm[row * 17 + part * 4 + 1] = v.y;
            sm[row * 17 + part * 4 + 2] = v.z;
            sm[row * 17 + part * 4 + 3] = v.w;
        }
        __syncthreads();
        {
            int e = t >> 4, dcol = (t & 15) * 4;
            int c = mat * 256 + h * 16 + e;
            __half* dst = &g_Wh1[(size_t)c * DM_ + d0 + dcol];
            *(__half2*)&dst[0] = __floats2half2_rn(sm[(dcol + 0) * 17 + e], sm[(dcol + 1) * 17 + e]);
            *(__half2*)&dst[2] = __floats2half2_rn(sm[(dcol + 2) * 17 + e], sm[(dcol + 3) * 17 + e]);
        }
    } else if (blk < PREP_W20) {
        int idx = (blk - PREP_V0) * 256 + t;
        g_Wh1[512 * DM_ + idx] = __float2half(WV[idx]);
    } else if (blk < PREP_CV0) {
        int rem = blk - PREP_W20;
        int n0 = (rem / 12) * 16, m0 = (rem % 12) * 64;
        {
            int row = t >> 4, part = t & 15;
            float4 v = *(const float4*)&WO[(size_t)(n0 + row) * DM_ + m0 + part * 4];
            sm[row * 65 + part * 4 + 0] = v.x;
            sm[row * 65 + part * 4 + 1] = v.y;
            sm[row * 65 + part * 4 + 2] = v.z;
            sm[row * 65 + part * 4 + 3] = v.w;
        }
        __syncthreads();
        {
            int mm = t >> 2, nn = (t & 3) * 4;
            __half* dst = &g_Wh2[(size_t)(m0 + mm) * NOV_ + n0 + nn];
            *(__half2*)&dst[0] = __floats2half2_rn(sm[(nn + 0) * 65 + mm], sm[(nn + 1) * 65 + mm]);
            *(__half2*)&dst[2] = __floats2half2_rn(sm[(nn + 2) * 65 + mm], sm[(nn + 3) * 65 + mm]);
        }
    } else if (blk < PREP_RT0) {
        int i = ((blk - PREP_CV0) * 256 + t) * 4;
        float4 v = *(const float4*)(resid + i);
        *(__half2*)&g_Ah[i]     = __floats2half2_rn(v.x, v.y);
        *(__half2*)&g_Ah[i + 2] = __floats2half2_rn(v.z, v.w);
    } else if (blk < PREP_VV0) {
        int idx = (blk - PREP_RT0) * 256 + t;
        int s = idx >> 3, i = idx & 7;
        float freq = powf(10000.f, (float)i / 8.f);
        float sn, cs;
        sincosf((float)s / freq, &sn, &cs);
        g_rot[s * 16 + i]     = sn;
        g_rot[s * 16 + 8 + i] = cs;
    } else {
        int idx = (blk - PREP_VV0) * 256 + t;
        int c = idx & 255;
        int m = (idx >> 8) & 15;
        int b = idx >> 12;
        int h = c >> 4, e = c & 15;
        size_t row = ((size_t)(b * NQK_ + h) * SK_ + S_ + m) * DQK_ + e;
        g_Kh[row] = __float2half(vk[m * 256 + c]);
        g_Vh[row] = __float2half(vv[m * 256 + c]);
    }
}

// ---------------------------------------------------------------------------
// 2) fp16 tensor-core GEMM: 64x64 tile, 128 threads (4 warps 2x2),
//    4-stage cp.async pipeline. Grid doubled vs 64x128 -> ~5 CTAs/SM.
//    MODE 0: C = A*B^T + bias; MODE 1: fused QKV bias/rotary/scatter epilogue
// ---------------------------------------------------------------------------
#define BKH 32
#define LDT 40
#define HG_STAGES 4
#define HG_A_HALVES (64 * LDT)
#define HG_B_HALVES (64 * LDT)
#define HG_SMEM_BYTES (HG_STAGES * (HG_A_HALVES + HG_B_HALVES) * 2)   // 40960

template<int MODE>
__global__ __launch_bounds__(128)
void hgemm(const __half* __restrict__ A, const __half* __restrict__ Bm,
           float* __restrict__ C, int M, int N, int K,
           const float* __restrict__ bias,
           const float* __restrict__ bQv,
           const float* __restrict__ bKv,
           const float* __restrict__ bVv)
{
    extern __shared__ __half smh[];
    __half* Asm = smh;
    __half* Bsm = smh + HG_STAGES * HG_A_HALVES;

    const int tid  = threadIdx.x;
    const int warp = tid >> 5, lane = tid & 31;
    const int wm = warp >> 1, wn = warp & 1;          // 2 x 2 warps
    const int bm = blockIdx.y * 64, bn = blockIdx.x * 64;

    // staging: 64 rows x 32 halves for A and B; row=tid/2, 2 chunks of 16B
    const int row  = tid >> 1;
    const int koff = (tid & 1) * 16;

    const __half* Ag = A + (size_t)(bm + row) * K + koff;
    const __half* Bg = Bm + (size_t)(bn + row) * K + koff;
    const uint32_t AsB = smem_u32(Asm);
    const uint32_t BsB = smem_u32(Bsm);
    const uint32_t stO = (uint32_t)(row * LDT + koff) * 2;
    const uint32_t SA = HG_A_HALVES * 2;              // 5120 B
    const uint32_t SB = HG_B_HALVES * 2;

    const int mat = lane >> 3, r = lane & 7;
    const uint32_t a_off = (uint32_t)((wm * 32 + (mat & 1) * 8 + r) * LDT + (mat >> 1) * 8) * 2;
    const uint32_t b_off = (uint32_t)((wn * 32 + (mat >> 1) * 8 + r) * LDT + (mat & 1) * 8) * 2;

    float acc[2][4][4];
#pragma unroll
    for (int i = 0; i < 2; i++)
#pragma unroll
        for (int j = 0; j < 4; j++)
#pragma unroll
            for (int tt = 0; tt < 4; tt++) acc[i][j][tt] = 0.f;

    const int KT = K / BKH;

#pragma unroll
    for (int s = 0; s < 3; s++) {
        cp16(AsB + s * SA + stO,      Ag + s * BKH);
        cp16(AsB + s * SA + stO + 16, Ag + s * BKH + 8);
        cp16(BsB + s * SB + stO,      Bg + s * BKH);
        cp16(BsB + s * SB + stO + 16, Bg + s * BKH + 8);
        asm volatile("cp.async.commit_group;");
    }
    asm volatile("cp.async.wait_group 2;" ::: "memory");
    __syncthreads();

    int stage = 0;
    for (int kt = 0; kt < KT; kt++) {
        const uint32_t Abuf = AsB + (uint32_t)stage * SA;
        const uint32_t Bbuf = BsB + (uint32_t)stage * SB;
#pragma unroll
        for (int ks = 0; ks < 2; ks++) {
            uint32_t a[2][4];
#pragma unroll
            for (int mt = 0; mt < 2; mt++)
                ldm4(a[mt][0], a[mt][1], a[mt][2], a[mt][3],
                     Abuf + a_off + (uint32_t)(mt * 16 * LDT + ks * 16) * 2);
            uint32_t bf[4][2];
#pragma unroll
            for (int p = 0; p < 2; p++) {
                uint32_t r0, r1, r2, r3;
                ldm4(r0, r1, r2, r3,
                     Bbuf + b_off + (uint32_t)(p * 16 * LDT + ks * 16) * 2);
                bf[2 * p][0] = r0; bf[2 * p][1] = r1;
                bf[2 * p + 1][0] = r2; bf[2 * p + 1][1] = r3;
            }
#pragma unroll
            for (int mt = 0; mt < 2; mt++)
#pragma unroll
                for (int nt = 0; nt < 4; nt++)
                    mma16816(acc[mt][nt], a[mt], bf[nt]);
        }

        if (kt + 3 < KT) {
            const int ns = (stage + 3 >= HG_STAGES) ? stage + 3 - HG_STAGES : stage + 3;
            const __half* ag = Ag + (kt + 3) * BKH;
            const __half* bg = Bg + (kt + 3) * BKH;
            cp16(AsB + (uint32_t)ns * SA + stO,      ag);
            cp16(AsB + (uint32_t)ns * SA + stO + 16, ag + 8);
            cp16(BsB + (uint32_t)ns * SB + stO,      bg);
            cp16(BsB + (uint32_t)ns * SB + stO + 16, bg + 8);
            asm volatile("cp.async.commit_group;");
            asm volatile("cp.async.wait_group 2;" ::: "memory");
        } else {
            asm volatile("cp.async.wait_group 0;" ::: "memory");
        }
        __syncthreads();
        stage = (stage + 1 >= HG_STAGES) ? 0 : stage + 1;
    }

    if (MODE == 0) {
#pragma unroll
        for (int mt = 0; mt < 2; mt++) {
            const int r0 = bm + wm * 32 + mt * 16 + (lane >> 2);
#pragma unroll
            for (int nt = 0; nt < 4; nt++) {
                const int c0 = bn + wn * 32 + nt * 8 + (lane & 3) * 2;
                float b0 = bias[c0], b1 = bias[c0 + 1];
                float2 v01 = { acc[mt][nt][0] + b0, acc[mt][nt][1] + b1 };
                float2 v23 = { acc[mt][nt][2] + b0, acc[mt][nt][3] + b1 };
                *(float2*)(C + (size_t)r0 * N + c0)       = v01;
                *(float2*)(C + (size_t)(r0 + 8) * N + c0) = v23;
            }
        }
    } else {
        const int i = (lane & 3) * 2;
#pragma unroll
        for (int mt = 0; mt < 2; mt++) {
            const int r0 = bm + wm * 32 + mt * 16 + (lane >> 2);
#pragma unroll
            for (int rr = 0; rr < 2; rr++) {
                const int row2 = r0 + rr * 8;
                const int s = row2 & (S_ - 1);
                const int b = row2 >> 11;
                const float* rt = &g_rot[s * 16];
#pragma unroll
                for (int np = 0; np < 2; np++) {
                    const int base = bn + wn * 32 + np * 16;
                    const float vlo0 = acc[mt][2 * np][2 * rr + 0];
                    const float vlo1 = acc[mt][2 * np][2 * rr + 1];
                    const float vhi0 = acc[mt][2 * np + 1][2 * rr + 0];
                    const float vhi1 = acc[mt][2 * np + 1][2 * rr + 1];
                    if (base < 256) {
                        const int h = base >> 4;
                        float a0 = vlo0 + bQv[h * 16 + i];
                        float a1 = vlo1 + bQv[h * 16 + i + 1];
                        float c0 = vhi0 + bQv[h * 16 + i + 8];
                        float c1 = vhi1 + bQv[h * 16 + i + 9];
                        float sn0 = rt[i], sn1 = rt[i + 1];
                        float cs0 = rt[8 + i], cs1 = rt[9 + i];
                        __half* dst = &g_Qh[((size_t)(b * NQK_ + h) * S_ + s) * DQK_];
                        *(__half2*)&dst[i]     = __floats2half2_rn((a0 * cs0 - c0 * sn0) * QSCALE,
                                                                   (a1 * cs1 - c1 * sn1) * QSCALE);
                        *(__half2*)&dst[i + 8] = __floats2half2_rn((c0 * cs0 + a0 * sn0) * QSCALE,
                                                                   (c1 * cs1 + a1 * sn1) * QSCALE);
                    } else if (base < 512) {
                        const int h = (base - 256) >> 4;
                        float a0 = vlo0 + bKv[h * 16 + i];
                        float a1 = vlo1 + bKv[h * 16 + i + 1];
                        float c0 = vhi0 + bKv[h * 16 + i + 8];
                        float c1 = vhi1 + bKv[h * 16 + i + 9];
                        float sn0 = rt[i], sn1 = rt[i + 1];
                        float cs0 = rt[8 + i], cs1 = rt[9 + i];
                        __half* dst = &g_Kh[((size_t)(b * NQK_ + h) * SK_ + s) * DQK_];
                        *(__half2*)&dst[i]     = __floats2half2_rn(a0 * cs0 - c0 * sn0,
                                                                   a1 * cs1 - c1 * sn1);
                        *(__half2*)&dst[i + 8] = __floats2half2_rn(c0 * cs0 + a0 * sn0,
                                                                   c1 * cs1 + a1 * sn1);
                    } else {
                        const int n0 = base - 512;
                        const int h = n0 >> 4;
                        __half* dst = &g_Vh[((size_t)(b * NQK_ + h) * SK_ + s) * DQK_];
                        *(__half2*)&dst[i]     = __floats2half2_rn(vlo0 + bVv[n0 + i],
                                                                   vlo1 + bVv[n0 + i + 1]);
                        *(__half2*)&dst[i + 8] = __floats2half2_rn(vhi0 + bVv[n0 + i + 8],
                                                                   vhi1 + bVv[n0 + i + 9]);
                    }
                }
            }
        }
    }
}

// ---------------------------------------------------------------------------
// 3) Flash attention (unchanged from R11): antithetic pairing + full-tile
//    single-softmax fast path; diag tile chunked + guards.
// ---------------------------------------------------------------------------
#define PAD 24

__global__ __launch_bounds__(128, 5)
void attn_mma()
{
    const int bh   = blockIdx.y;
    const int pp   = blockIdx.x;          // 0..15
    const int tid  = threadIdx.x;
    const int warp = tid >> 5, lane = tid & 31;

    __shared__ __half Qs[64 * PAD];
    __shared__ __half K0s[16 * PAD];
    __shared__ __half V0s[16 * PAD];
    __shared__ __half Ks[2][128 * PAD];
    __shared__ __half Vs[2][128 * PAD];

    const __half* Kg = g_Kh + (size_t)bh * SK_ * DQK_;
    const __half* Vg = g_Vh + (size_t)bh * SK_ * DQK_;

    const int ld_row = tid >> 1;
    const int ld_off = (tid & 1) * 8;

    if (tid < 32) {
        int pr = tid >> 1, po = (tid & 1) * 8;
        cp16(smem_u32(&K0s[pr * PAD + po]), Kg + (size_t)pr * 16 + po);
        cp16(smem_u32(&V0s[pr * PAD + po]), Vg + (size_t)pr * 16 + po);
    }
    asm volatile("cp.async.commit_group;");

    const int g = lane >> 3, r = lane & 7;
    const int qfrow = warp * 16 + (g & 1) * 8 + r;
    const int qfcol = (g >> 1) * 8;
    const int krow = (g >> 1) * 8 + r;
    const int kcol = (g & 1) * 8;
    const int vrow = (g & 1) * 8 + r;
    const int vcol = (g >> 1) * 8;
    const uint32_t onesb[2] = { 0x3C003C00u, 0x3C003C00u };

#pragma unroll 1
    for (int sel = 0; sel < 2; sel++) {
        const int qt = sel ? pp : (31 - pp);
        const int q0 = qt * 64;
        const __half* Qg = g_Qh + ((size_t)bh * S_ + q0) * DQK_;

        __syncthreads();

        *(float4*)&Qs[ld_row * PAD + ld_off] =
            *(const float4*)&Qg[(size_t)ld_row * 16 + ld_off];

        cp16(smem_u32(&Ks[0][ld_row * PAD + ld_off]),        Kg + (size_t)(16 + ld_row) * 16 + ld_off);
        cp16(smem_u32(&Ks[0][(ld_row + 64) * PAD + ld_off]), Kg + (size_t)(80 + ld_row) * 16 + ld_off);
        cp16(smem_u32(&Vs[0][ld_row * PAD + ld_off]),        Vg + (size_t)(16 + ld_row) * 16 + ld_off);
        cp16(smem_u32(&Vs[0][(ld_row + 64) * PAD + ld_off]), Vg + (size_t)(80 + ld_row) * 16 + ld_off);
        asm volatile("cp.async.commit_group;");

        asm volatile("cp.async.wait_group 1;" ::: "memory");
        __syncthreads();

        uint32_t qa[4];
        ldm4(qa[0], qa[1], qa[2], qa[3], smem_u32(&Qs[qfrow * PAD + qfcol]));

        float m0, m1;
        float o[2][4] = {{0.f,0.f,0.f,0.f},{0.f,0.f,0.f,0.f}};
        float oL[4]   = {0.f,0.f,0.f,0.f};

        // ---- prologue: 16 keys, unmasked ----
        {
            float sc[2][4] = {{0.f,0.f,0.f,0.f},{0.f,0.f,0.f,0.f}};
            uint32_t b0, b1, b2, b3;
            ldm4(b0, b1, b2, b3, smem_u32(&K0s[krow * PAD + kcol]));
            {
                uint32_t bl[2] = { b0, b1 }, bh2[2] = { b2, b3 };
                mma16816(sc[0], qa, bl);
                mma16816(sc[1], qa, bh2);
            }
            float rm0 = fmaxf(fmaxf(sc[0][0], sc[0][1]), fmaxf(sc[1][0], sc[1][1]));
            float rm1 = fmaxf(fmaxf(sc[0][2], sc[0][3]), fmaxf(sc[1][2], sc[1][3]));
            rm0 = fmaxf(rm0, __shfl_xor_sync(0xffffffff, rm0, 1));
            rm0 = fmaxf(rm0, __shfl_xor_sync(0xffffffff, rm0, 2));
            rm1 = fmaxf(rm1, __shfl_xor_sync(0xffffffff, rm1, 1));
            rm1 = fmaxf(rm1, __shfl_xor_sync(0xffffffff, rm1, 2));
            m0 = rm0; m1 = rm1;

            uint32_t pa[4];
            pa[0] = ex2h2(sc[0][0] - m0, sc[0][1] - m0);
            pa[1] = ex2h2(sc[0][2] - m1, sc[0][3] - m1);
            pa[2] = ex2h2(sc[1][0] - m0, sc[1][1] - m0);
            pa[3] = ex2h2(sc[1][2] - m1, sc[1][3] - m1);

            uint32_t v0, v1, v2, v3;
            ldm4t(v0, v1, v2, v3, smem_u32(&V0s[vrow * PAD + vcol]));
            uint32_t bl[2] = { v0, v1 }, bh2[2] = { v2, v3 };
            mma16816(o[0], pa, bl);
            mma16816(o[1], pa, bh2);
            mma16816(oL,   pa, onesb);
        }

        const int jmax = (q0 + 63) >> 7;

        for (int jt = 0; jt <= jmax; jt++) {
            const int buf = jt & 1;
            if (jt < jmax) {
                const size_t kb = (size_t)(16 + (jt + 1) * 128);
                cp16(smem_u32(&Ks[buf ^ 1][ld_row * PAD + ld_off]),        Kg + (kb + ld_row) * 16 + ld_off);
                cp16(smem_u32(&Ks[buf ^ 1][(ld_row + 64) * PAD + ld_off]), Kg + (kb + ld_row + 64) * 16 + ld_off);
                cp16(smem_u32(&Vs[buf ^ 1][ld_row * PAD + ld_off]),        Vg + (kb + ld_row) * 16 + ld_off);
                cp16(smem_u32(&Vs[buf ^ 1][(ld_row + 64) * PAD + ld_off]), Vg + (kb + ld_row + 64) * 16 + ld_off);
                asm volatile("cp.async.commit_group;");
                asm volatile("cp.async.wait_group 1;" ::: "memory");
            } else {
                asm volatile("cp.async.wait_group 0;" ::: "memory");
            }
            __syncthreads();

            if (jt < jmax) {
                // ===== FULL TILE: 128 keys, single softmax update =====
                float sc[16][4];
#pragma unroll
                for (int nt = 0; nt < 16; nt++)
#pragma unroll
                    for (int tt = 0; tt < 4; tt++) sc[nt][tt] = 0.f;

#pragma unroll
                for (int i = 0; i < 8; i++) {
                    uint32_t b0, b1, b2, b3;
                    ldm4(b0, b1, b2, b3,
                         smem_u32(&Ks[buf][(16 * i + krow) * PAD + kcol]));
                    uint32_t bl[2] = { b0, b1 }, bh2[2] = { b2, b3 };
                    mma16816(sc[2 * i],     qa, bl);
                    mma16816(sc[2 * i + 1], qa, bh2);
                }

                float rm0 = sc[0][0], rm1 = sc[0][2];
#pragma unroll
                for (int nt = 0; nt < 16; nt++) {
                    rm0 = fmaxf(rm0, fmaxf(sc[nt][0], sc[nt][1]));
                    rm1 = fmaxf(rm1, fmaxf(sc[nt][2], sc[nt][3]));
                }
                rm0 = fmaxf(rm0, __shfl_xor_sync(0xffffffff, rm0, 1));
                rm0 = fmaxf(rm0, __shfl_xor_sync(0xffffffff, rm0, 2));
                rm1 = fmaxf(rm1, __shfl_xor_sync(0xffffffff, rm1, 1));
                rm1 = fmaxf(rm1, __shfl_xor_sync(0xffffffff, rm1, 2));

                const float mn0 = fmaxf(m0, rm0);
                const float mn1 = fmaxf(m1, rm1);
                const float c0 = ex2f(m0 - mn0);
                const float c1 = ex2f(m1 - mn1);
                m0 = mn0; m1 = mn1;
                o[0][0] *= c0; o[0][1] *= c0; o[0][2] *= c1; o[0][3] *= c1;
                o[1][0] *= c0; o[1][1] *= c0; o[1][2] *= c1; o[1][3] *= c1;
                oL[0]   *= c0; oL[1]   *= c0; oL[2]   *= c1; oL[3]   *= c1;

#pragma unroll
                for (int kt = 0; kt < 8; kt++) {
                    uint32_t pa[4];
                    pa[0] = ex2h2(sc[2 * kt][0] - mn0,     sc[2 * kt][1] - mn0);
                    pa[1] = ex2h2(sc[2 * kt][2] - mn1,     sc[2 * kt][3] - mn1);
                    pa[2] = ex2h2(sc[2 * kt + 1][0] - mn0, sc[2 * kt + 1][1] - mn0);
                    pa[3] = ex2h2(sc[2 * kt + 1][2] - mn1, sc[2 * kt + 1][3] - mn1);
                    uint32_t v0, v1, v2, v3;
                    ldm4t(v0, v1, v2, v3,
                          smem_u32(&Vs[buf][(16 * kt + vrow) * PAD + vcol]));
                    uint32_t bl[2] = { v0, v1 }, bh2[2] = { v2, v3 };
                    mma16816(o[0], pa, bl);
                    mma16816(o[1], pa, bh2);
                    mma16816(oL,   pa, onesb);
                }
            } else {
                // ===== DIAG TILE: chunked + warp-uniform skips + mask =====
                const int off = q0 - 128 * jt;
                const int wb  = off + warp * 16 + 15;

#pragma unroll
                for (int c = 0; c < 2; c++) {
                    if (c * 64 <= wb) {
                        float sc[8][4];
#pragma unroll
                        for (int nt = 0; nt < 8; nt++)
#pragma unroll
                            for (int tt = 0; tt < 4; tt++) sc[nt][tt] = 0.f;

#pragma unroll
                        for (int i = 0; i < 4; i++) {
                            if ((c * 64 + i * 16) <= wb) {
                                uint32_t b0, b1, b2, b3;
                                ldm4(b0, b1, b2, b3,
                                     smem_u32(&Ks[buf][(16 * (c * 4 + i) + krow) * PAD + kcol]));
                                uint32_t bl[2] = { b0, b1 }, bh2[2] = { b2, b3 };
                                mma16816(sc[2 * i],     qa, bl);
                                mma16816(sc[2 * i + 1], qa, bh2);
                            }
                        }

                        {
                            const int jb = c * 64 + (lane & 3) * 2;
                            const int t0 = off + warp * 16 + (lane >> 2);
                            const int t1 = t0 + 8;
#pragma unroll
                            for (int nt = 0; nt < 8; nt++) {
                                int j0 = jb + nt * 8;
                                if (j0     > t0) sc[nt][0] = -1e30f;
                                if (j0 + 1 > t0) sc[nt][1] = -1e30f;
                                if (j0     > t1) sc[nt][2] = -1e30f;
                                if (j0 + 1 > t1) sc[nt][3] = -1e30f;
                            }
                        }

                        float rm0 = sc[0][0], rm1 = sc[0][2];
#pragma unroll
                        for (int nt = 0; nt < 8; nt++) {
                            rm0 = fmaxf(rm0, fmaxf(sc[nt][0], sc[nt][1]));
                            rm1 = fmaxf(rm1, fmaxf(sc[nt][2], sc[nt][3]));
                        }
                        rm0 = fmaxf(rm0, __shfl_xor_sync(0xffffffff, rm0, 1));
                        rm0 = fmaxf(rm0, __shfl_xor_sync(0xffffffff, rm0, 2));
                        rm1 = fmaxf(rm1, __shfl_xor_sync(0xffffffff, rm1, 1));
                        rm1 = fmaxf(rm1, __shfl_xor_sync(0xffffffff, rm1, 2));

                        const float mn0 = fmaxf(m0, rm0);
                        const float mn1 = fmaxf(m1, rm1);
                        const float c0 = ex2f(m0 - mn0);
                        const float c1 = ex2f(m1 - mn1);
                        m0 = mn0; m1 = mn1;
                        o[0][0] *= c0; o[0][1] *= c0; o[0][2] *= c1; o[0][3] *= c1;
                        o[1][0] *= c0; o[1][1] *= c0; o[1][2] *= c1; o[1][3] *= c1;
                        oL[0]   *= c0; oL[1]   *= c0; oL[2]   *= c1; oL[3]   *= c1;

#pragma unroll
                        for (int kt = 0; kt < 4; kt++) {
                            if ((c * 64 + kt * 16) <= wb) {
                                uint32_t pa[4];
                                pa[0] = ex2h2(sc[2 * kt][0] - mn0,     sc[2 * kt][1] - mn0);
                                pa[1] = ex2h2(sc[2 * kt][2] - mn1,     sc[2 * kt][3] - mn1);
                                pa[2] = ex2h2(sc[2 * kt + 1][0] - mn0, sc[2 * kt + 1][1] - mn0);
                                pa[3] = ex2h2(sc[2 * kt + 1][2] - mn1, sc[2 * kt + 1][3] - mn1);
                                uint32_t v0, v1, v2, v3;
                                ldm4t(v0, v1, v2, v3,
                                      smem_u32(&Vs[buf][(16 * (c * 4 + kt) + vrow) * PAD + vcol]));
                                uint32_t bl[2] = { v0, v1 }, bh2[2] = { v2, v3 };
                                mma16816(o[0], pa, bl);
                                mma16816(o[1], pa, bh2);
                                mma16816(oL,   pa, onesb);
                            }
                        }
                    }
                }
            }
            __syncthreads();
        }

        const float inv0 = 1.f / oL[0];
        const float inv1 = 1.f / oL[2];

        const int qrow0 = q0 + warp * 16 + (lane >> 2);
        const int b = bh >> 4, h = bh & 15;
        const int col = (lane & 3) * 2;
#pragma unroll
        for (int vt = 0; vt < 2; vt++) {
            uint32_t lo = packh2(o[vt][0] * inv0, o[vt][1] * inv0);
            uint32_t hi = packh2(o[vt][2] * inv1, o[vt][3] * inv1);
            size_t base0 = ((size_t)(b * S_ + qrow0)     ) * NOV_ + h * 16 + vt * 8 + col;
            size_t base1 = ((size_t)(b * S_ + qrow0 + 8) ) * NOV_ + h * 16 + vt * 8 + col;
            *(uint32_t*)&g_Zh[base0] = lo;
            *(uint32_t*)&g_Zh[base1] = hi;
        }
    }
}

// ---------------------------------------------------------------------------
// Launch
// ---------------------------------------------------------------------------
extern "C" void kernel_launch(void* const* d_in, const int* in_sizes, int n_in,
                              void* d_out, int out_size)
{
    const float* resid = (const float*)d_in[0];
    const float* W_Q   = (const float*)d_in[1];
    const float* W_K   = (const float*)d_in[2];
    const float* W_V   = (const float*)d_in[3];
    const float* W_O   = (const float*)d_in[4];
    const float* b_Q   = (const float*)d_in[5];
    const float* b_K   = (const float*)d_in[6];
    const float* b_V   = (const float*)d_in[7];
    const float* b_O   = (const float*)d_in[8];
    const float* v_k   = (const float*)d_in[9];
    const float* v_v   = (const float*)d_in[10];
    float* out = (float*)d_out;

    __half *Ah, *Wh1, *Wh2, *Zh;
    cudaGetSymbolAddress((void**)&Ah,  g_Ah);
    cudaGetSymbolAddress((void**)&Wh1, g_Wh1);
    cudaGetSymbolAddress((void**)&Wh2, g_Wh2);
    cudaGetSymbolAddress((void**)&Zh,  g_Zh);

    cudaFuncSetAttribute(hgemm<0>, cudaFuncAttributeMaxDynamicSharedMemorySize, HG_SMEM_BYTES);
    cudaFuncSetAttribute(hgemm<1>, cudaFuncAttributeMaxDynamicSharedMemorySize, HG_SMEM_BYTES);

    // 1) fused prep
    prep_kernel<<<PREP_BLKS, 256>>>(W_Q, W_K, W_V, W_O, resid, v_k, v_v);

    // 2) GEMM1 + fused bias/rotary/scatter epilogue -> g_Qh/g_Kh/g_Vh
    {
        dim3 grid(DM_ / 64, BS_ / 64);
        hgemm<1><<<grid, 128, HG_SMEM_BYTES>>>(Ah, Wh1, nullptr, BS_, DM_, DM_,
                                               nullptr, b_Q, b_K, b_V);
    }

    // 3) tensor-core flash attention
    {
        dim3 grid(16, B_ * NQK_);
        attn_mma<<<grid, 128>>>();
    }

    // 4) GEMM2: (4096 x 768) = Zh * Wh2^T + b_O -> out fp32
    {
        dim3 grid(DM_ / 64, BS_ / 64);
        hgemm<0><<<grid, 128, HG_SMEM_BYTES>>>(Zh, Wh2, out, BS_, DM_, NOV_,
                                               b_O, nullptr, nullptr, nullptr);
    }
}

// round 13
// speedup vs baseline: 1.0446x; 1.0446x over previous
#include <cuda_runtime.h>
#include <cuda_fp16.h>
#include <cstdint>

// ---------------------------------------------------------------------------
// Problem constants
// ---------------------------------------------------------------------------
#define B_   2
#define S_   2048
#define DM_  768
#define NQK_ 16
#define DQK_ 16
#define NOV_ 256
#define VKV_ 16
#define SK_  (S_ + VKV_)     // 2064 keys = 16 + 16*128 (exact)
#define BS_  (B_ * S_)       // 4096 rows

// ---------------------------------------------------------------------------
// Device scratch
// ---------------------------------------------------------------------------
__device__ __half g_Ah  [BS_ * DM_];
__device__ __half g_Wh1 [DM_ * DM_];
__device__ __half g_Wh2 [DM_ * NOV_];
__device__ float  g_rot [S_ * 16];                  // [s][0..7]=sin, [8..15]=cos
__device__ __half g_Qh  [B_ * NQK_ * S_  * DQK_];
__device__ __half g_Kh  [B_ * NQK_ * SK_ * DQK_];
__device__ __half g_Vh  [B_ * NQK_ * SK_ * DQK_];
__device__ __half g_Zh  [BS_ * NOV_];

// ---------------------------------------------------------------------------
// helpers
// ---------------------------------------------------------------------------
__device__ __forceinline__ uint32_t smem_u32(const void* p) {
    return (uint32_t)__cvta_generic_to_shared(p);
}
__device__ __forceinline__ void cp16(uint32_t s, const void* g) {
    asm volatile("cp.async.cg.shared.global [%0], [%1], 16;" :: "r"(s), "l"(g));
}
__device__ __forceinline__ float ex2f(float x) {
    float y; asm("ex2.approx.ftz.f32 %0, %1;" : "=f"(y) : "f"(x)); return y;
}
__device__ __forceinline__ uint32_t ex2h2(float lo, float hi) {
    uint32_t h, r;
    asm("cvt.rn.f16x2.f32 %0, %1, %2;" : "=r"(h) : "f"(hi), "f"(lo));
    asm("ex2.approx.f16x2 %0, %1;" : "=r"(r) : "r"(h));
    return r;
}
__device__ __forceinline__ void ldm4(uint32_t& r0, uint32_t& r1, uint32_t& r2, uint32_t& r3, uint32_t addr) {
    asm volatile("ldmatrix.sync.aligned.m8n8.x4.shared.b16 {%0,%1,%2,%3}, [%4];"
                 : "=r"(r0), "=r"(r1), "=r"(r2), "=r"(r3) : "r"(addr));
}
__device__ __forceinline__ void ldm4t(uint32_t& r0, uint32_t& r1, uint32_t& r2, uint32_t& r3, uint32_t addr) {
    asm volatile("ldmatrix.sync.aligned.m8n8.x4.trans.shared.b16 {%0,%1,%2,%3}, [%4];"
                 : "=r"(r0), "=r"(r1), "=r"(r2), "=r"(r3) : "r"(addr));
}
__device__ __forceinline__ void mma16816(float* d, const uint32_t* a, const uint32_t* b) {
    asm volatile("mma.sync.aligned.m16n8k16.row.col.f32.f16.f16.f32 "
                 "{%0,%1,%2,%3},{%4,%5,%6,%7},{%8,%9},{%0,%1,%2,%3};"
                 : "+f"(d[0]), "+f"(d[1]), "+f"(d[2]), "+f"(d[3])
                 : "r"(a[0]), "r"(a[1]), "r"(a[2]), "r"(a[3]), "r"(b[0]), "r"(b[1]));
}
__device__ __forceinline__ uint32_t packh2(float x, float y) {
    __half2 h = __floats2half2_rn(x, y);
    return *(uint32_t*)&h;
}

#define QSCALE 0.36067376022224085f   // 0.25 * log2(e)

// ---------------------------------------------------------------------------
// 1) Fused prep (unchanged)
// ---------------------------------------------------------------------------
#define PREP_TQK0 0
#define PREP_V0   384
#define PREP_W20  1152
#define PREP_CV0  1344
#define PREP_RT0  4416
#define PREP_VV0  4480
#define PREP_BLKS 4512

__global__ void prep_kernel(const float* __restrict__ WQ,
                            const float* __restrict__ WK,
                            const float* __restrict__ WV,
                            const float* __restrict__ WO,
                            const float* __restrict__ resid,
                            const float* __restrict__ vk,
                            const float* __restrict__ vv)
{
    __shared__ float sm[64 * 17];
    const int blk = blockIdx.x;
    const int t = threadIdx.x;

    if (blk < PREP_V0) {
        int rem = blk, mat = rem / 192; rem %= 192;
        int h = rem / 12, d0 = (rem % 12) * 64;
        const float* W = mat ? WK : WQ;
        {
            int row = t >> 2, part = t & 3;
            float4 v = *(const float4*)&W[((size_t)h * DM_ + d0 + row) * DQK_ + part * 4];
            sm[row * 17 + part * 4 + 0] = v.x;
            sm[row * 17 + part * 4 + 1] = v.y;
            sm[row * 17 + part * 4 + 2] = v.z;
            sm[row * 17 + part * 4 + 3] = v.w;
        }
        __syncthreads();
        {
            int e = t >> 4, dcol = (t & 15) * 4;
            int c = mat * 256 + h * 16 + e;
            __half* dst = &g_Wh1[(size_t)c * DM_ + d0 + dcol];
            *(__half2*)&dst[0] = __floats2half2_rn(sm[(dcol + 0) * 17 + e], sm[(dcol + 1) * 17 + e]);
            *(__half2*)&dst[2] = __floats2half2_rn(sm[(dcol + 2) * 17 + e], sm[(dcol + 3) * 17 + e]);
        }
    } else if (blk < PREP_W20) {
        int idx = (blk - PREP_V0) * 256 + t;
        g_Wh1[512 * DM_ + idx] = __float2half(WV[idx]);
    } else if (blk < PREP_CV0) {
        int rem = blk - PREP_W20;
        int n0 = (rem / 12) * 16, m0 = (rem % 12) * 64;
        {
            int row = t >> 4, part = t & 15;
            float4 v = *(const float4*)&WO[(size_t)(n0 + row) * DM_ + m0 + part * 4];
            sm[row * 65 + part * 4 + 0] = v.x;
            sm[row * 65 + part * 4 + 1] = v.y;
            sm[row * 65 + part * 4 + 2] = v.z;
            sm[row * 65 + part * 4 + 3] = v.w;
        }
        __syncthreads();
        {
            int mm = t >> 2, nn = (t & 3) * 4;
            __half* dst = &g_Wh2[(size_t)(m0 + mm) * NOV_ + n0 + nn];
            *(__half2*)&dst[0] = __floats2half2_rn(sm[(nn + 0) * 65 + mm], sm[(nn + 1) * 65 + mm]);
            *(__half2*)&dst[2] = __floats2half2_rn(sm[(nn + 2) * 65 + mm], sm[(nn + 3) * 65 + mm]);
        }
    } else if (blk < PREP_RT0) {
        int i = ((blk - PREP_CV0) * 256 + t) * 4;
        float4 v = *(const float4*)(resid + i);
        *(__half2*)&g_Ah[i]     = __floats2half2_rn(v.x, v.y);
        *(__half2*)&g_Ah[i + 2] = __floats2half2_rn(v.z, v.w);
    } else if (blk < PREP_VV0) {
        int idx = (blk - PREP_RT0) * 256 + t;
        int s = idx >> 3, i = idx & 7;
        float freq = powf(10000.f, (float)i / 8.f);
        float sn, cs;
        sincosf((float)s / freq, &sn, &cs);
        g_rot[s * 16 + i]     = sn;
        g_rot[s * 16 + 8 + i] = cs;
    } else {
        int idx = (blk - PREP_VV0) * 256 + t;
        int c = idx & 255;
        int m = (idx >> 8) & 15;
        int b = idx >> 12;
        int h = c >> 4, e = c & 15;
        size_t row = ((size_t)(b * NQK_ + h) * SK_ + S_ + m) * DQK_ + e;
        g_Kh[row] = __float2half(vk[m * 256 + c]);
        g_Vh[row] = __float2half(vv[m * 256 + c]);
    }
}

// ---------------------------------------------------------------------------
// 2) fp16 tensor-core GEMM: 64x128 tile, 256 threads, 4-stage (R11 config)
// ---------------------------------------------------------------------------
#define BKH 32
#define LDT 40
#define HG_STAGES 4
#define HG_A_HALVES (64  * LDT)
#define HG_B_HALVES (128 * LDT)
#define HG_SMEM_BYTES (HG_STAGES * (HG_A_HALVES + HG_B_HALVES) * 2)

template<int MODE>
__global__ __launch_bounds__(256)
void hgemm(const __half* __restrict__ A, const __half* __restrict__ Bm,
           float* __restrict__ C, int M, int N, int K,
           const float* __restrict__ bias,
           const float* __restrict__ bQv,
           const float* __restrict__ bKv,
           const float* __restrict__ bVv)
{
    extern __shared__ __half smh[];
    __half* Asm = smh;
    __half* Bsm = smh + HG_STAGES * HG_A_HALVES;

    const int tid  = threadIdx.x;
    const int warp = tid >> 5, lane = tid & 31;
    const int wm = warp >> 2, wn = warp & 3;
    const int bm = blockIdx.y * 64, bn = blockIdx.x * 128;

    const int arow = tid >> 2;
    const int aoff = (tid & 3) * 8;
    const int brow = tid >> 1;
    const int boff = (tid & 1) * 16;

    const __half* Ag = A + (size_t)(bm + arow) * K + aoff;
    const __half* Bg = Bm + (size_t)(bn + brow) * K + boff;
    const uint32_t AsB = smem_u32(Asm);
    const uint32_t BsB = smem_u32(Bsm);
    const uint32_t stA = (uint32_t)(arow * LDT + aoff) * 2;
    const uint32_t stB = (uint32_t)(brow * LDT + boff) * 2;
    const uint32_t SA = HG_A_HALVES * 2;
    const uint32_t SB = HG_B_HALVES * 2;

    const int mat = lane >> 3, r = lane & 7;
    const uint32_t a_off = (uint32_t)((wm * 32 + (mat & 1) * 8 + r) * LDT + (mat >> 1) * 8) * 2;
    const uint32_t b_off = (uint32_t)((wn * 32 + (mat >> 1) * 8 + r) * LDT + (mat & 1) * 8) * 2;

    float acc[2][4][4];
#pragma unroll
    for (int i = 0; i < 2; i++)
#pragma unroll
        for (int j = 0; j < 4; j++)
#pragma unroll
            for (int tt = 0; tt < 4; tt++) acc[i][j][tt] = 0.f;

    const int KT = K / BKH;

#pragma unroll
    for (int s = 0; s < 3; s++) {
        cp16(AsB + s * SA + stA,      Ag + s * BKH);
        cp16(BsB + s * SB + stB,      Bg + s * BKH);
        cp16(BsB + s * SB + stB + 16, Bg + s * BKH + 8);
        asm volatile("cp.async.commit_group;");
    }
    asm volatile("cp.async.wait_group 2;" ::: "memory");
    __syncthreads();

    int stage = 0;
    for (int kt = 0; kt < KT; kt++) {
        const uint32_t Abuf = AsB + (uint32_t)stage * SA;
        const uint32_t Bbuf = BsB + (uint32_t)stage * SB;
#pragma unroll
        for (int ks = 0; ks < 2; ks++) {
            uint32_t a[2][4];
#pragma unroll
            for (int mt = 0; mt < 2; mt++)
                ldm4(a[mt][0], a[mt][1], a[mt][2], a[mt][3],
                     Abuf + a_off + (uint32_t)(mt * 16 * LDT + ks * 16) * 2);
            uint32_t bf[4][2];
#pragma unroll
            for (int p = 0; p < 2; p++) {
                uint32_t r0, r1, r2, r3;
                ldm4(r0, r1, r2, r3,
                     Bbuf + b_off + (uint32_t)(p * 16 * LDT + ks * 16) * 2);
                bf[2 * p][0] = r0; bf[2 * p][1] = r1;
                bf[2 * p + 1][0] = r2; bf[2 * p + 1][1] = r3;
            }
#pragma unroll
            for (int mt = 0; mt < 2; mt++)
#pragma unroll
                for (int nt = 0; nt < 4; nt++)
                    mma16816(acc[mt][nt], a[mt], bf[nt]);
        }

        if (kt + 3 < KT) {
            const int ns = (stage + 3 >= HG_STAGES) ? stage + 3 - HG_STAGES : stage + 3;
            const __half* ag = Ag + (kt + 3) * BKH;
            const __half* bg = Bg + (kt + 3) * BKH;
            cp16(AsB + (uint32_t)ns * SA + stA,      ag);
            cp16(BsB + (uint32_t)ns * SB + stB,      bg);
            cp16(BsB + (uint32_t)ns * SB + stB + 16, bg + 8);
            asm volatile("cp.async.commit_group;");
            asm volatile("cp.async.wait_group 2;" ::: "memory");
        } else {
            asm volatile("cp.async.wait_group 0;" ::: "memory");
        }
        __syncthreads();
        stage = (stage + 1 >= HG_STAGES) ? 0 : stage + 1;
    }

    if (MODE == 0) {
#pragma unroll
        for (int mt = 0; mt < 2; mt++) {
            const int r0 = bm + wm * 32 + mt * 16 + (lane >> 2);
#pragma unroll
            for (int nt = 0; nt < 4; nt++) {
                const int c0 = bn + wn * 32 + nt * 8 + (lane & 3) * 2;
                float b0 = bias[c0], b1 = bias[c0 + 1];
                float2 v01 = { acc[mt][nt][0] + b0, acc[mt][nt][1] + b1 };
                float2 v23 = { acc[mt][nt][2] + b0, acc[mt][nt][3] + b1 };
                *(float2*)(C + (size_t)r0 * N + c0)       = v01;
                *(float2*)(C + (size_t)(r0 + 8) * N + c0) = v23;
            }
        }
    } else {
        const int i = (lane & 3) * 2;
#pragma unroll
        for (int mt = 0; mt < 2; mt++) {
            const int r0 = bm + wm * 32 + mt * 16 + (lane >> 2);
#pragma unroll
            for (int rr = 0; rr < 2; rr++) {
                const int row = r0 + rr * 8;
                const int s = row & (S_ - 1);
                const int b = row >> 11;
                const float* rt = &g_rot[s * 16];
#pragma unroll
                for (int np = 0; np < 2; np++) {
                    const int base = bn + wn * 32 + np * 16;
                    const float vlo0 = acc[mt][2 * np][2 * rr + 0];
                    const float vlo1 = acc[mt][2 * np][2 * rr + 1];
                    const float vhi0 = acc[mt][2 * np + 1][2 * rr + 0];
                    const float vhi1 = acc[mt][2 * np + 1][2 * rr + 1];
                    if (base < 256) {
                        const int h = base >> 4;
                        float a0 = vlo0 + bQv[h * 16 + i];
                        float a1 = vlo1 + bQv[h * 16 + i + 1];
                        float c0 = vhi0 + bQv[h * 16 + i + 8];
                        float c1 = vhi1 + bQv[h * 16 + i + 9];
                        float sn0 = rt[i], sn1 = rt[i + 1];
                        float cs0 = rt[8 + i], cs1 = rt[9 + i];
                        __half* dst = &g_Qh[((size_t)(b * NQK_ + h) * S_ + s) * DQK_];
                        *(__half2*)&dst[i]     = __floats2half2_rn((a0 * cs0 - c0 * sn0) * QSCALE,
                                                                   (a1 * cs1 - c1 * sn1) * QSCALE);
                        *(__half2*)&dst[i + 8] = __floats2half2_rn((c0 * cs0 + a0 * sn0) * QSCALE,
                                                                   (c1 * cs1 + a1 * sn1) * QSCALE);
                    } else if (base < 512) {
                        const int h = (base - 256) >> 4;
                        float a0 = vlo0 + bKv[h * 16 + i];
                        float a1 = vlo1 + bKv[h * 16 + i + 1];
                        float c0 = vhi0 + bKv[h * 16 + i + 8];
                        float c1 = vhi1 + bKv[h * 16 + i + 9];
                        float sn0 = rt[i], sn1 = rt[i + 1];
                        float cs0 = rt[8 + i], cs1 = rt[9 + i];
                        __half* dst = &g_Kh[((size_t)(b * NQK_ + h) * SK_ + s) * DQK_];
                        *(__half2*)&dst[i]     = __floats2half2_rn(a0 * cs0 - c0 * sn0,
                                                                   a1 * cs1 - c1 * sn1);
                        *(__half2*)&dst[i + 8] = __floats2half2_rn(c0 * cs0 + a0 * sn0,
                                                                   c1 * cs1 + a1 * sn1);
                    } else {
                        const int n0 = base - 512;
                        const int h = n0 >> 4;
                        __half* dst = &g_Vh[((size_t)(b * NQK_ + h) * SK_ + s) * DQK_];
                        *(__half2*)&dst[i]     = __floats2half2_rn(vlo0 + bVv[n0 + i],
                                                                   vlo1 + bVv[n0 + i + 1]);
                        *(__half2*)&dst[i + 8] = __floats2half2_rn(vhi0 + bVv[n0 + i + 8],
                                                                   vhi1 + bVv[n0 + i + 9]);
                    }
                }
            }
        }
    }
}

// ---------------------------------------------------------------------------
// 3) Flash attention (R11 + tree-max + no final-tile barrier)
// ---------------------------------------------------------------------------
#define PAD 24

__global__ __launch_bounds__(128, 5)
void attn_mma()
{
    const int bh   = blockIdx.y;
    const int pp   = blockIdx.x;          // 0..15
    const int tid  = threadIdx.x;
    const int warp = tid >> 5, lane = tid & 31;

    __shared__ __half Qs[64 * PAD];
    __shared__ __half K0s[16 * PAD];
    __shared__ __half V0s[16 * PAD];
    __shared__ __half Ks[2][128 * PAD];
    __shared__ __half Vs[2][128 * PAD];

    const __half* Kg = g_Kh + (size_t)bh * SK_ * DQK_;
    const __half* Vg = g_Vh + (size_t)bh * SK_ * DQK_;

    const int ld_row = tid >> 1;
    const int ld_off = (tid & 1) * 8;

    if (tid < 32) {
        int pr = tid >> 1, po = (tid & 1) * 8;
        cp16(smem_u32(&K0s[pr * PAD + po]), Kg + (size_t)pr * 16 + po);
        cp16(smem_u32(&V0s[pr * PAD + po]), Vg + (size_t)pr * 16 + po);
    }
    asm volatile("cp.async.commit_group;");

    const int g = lane >> 3, r = lane & 7;
    const int qfrow = warp * 16 + (g & 1) * 8 + r;
    const int qfcol = (g >> 1) * 8;
    const int krow = (g >> 1) * 8 + r;
    const int kcol = (g & 1) * 8;
    const int vrow = (g & 1) * 8 + r;
    const int vcol = (g >> 1) * 8;
    const uint32_t onesb[2] = { 0x3C003C00u, 0x3C003C00u };

#pragma unroll 1
    for (int sel = 0; sel < 2; sel++) {
        const int qt = sel ? pp : (31 - pp);
        const int q0 = qt * 64;
        const __half* Qg = g_Qh + ((size_t)bh * S_ + q0) * DQK_;

        __syncthreads();

        *(float4*)&Qs[ld_row * PAD + ld_off] =
            *(const float4*)&Qg[(size_t)ld_row * 16 + ld_off];

        cp16(smem_u32(&Ks[0][ld_row * PAD + ld_off]),        Kg + (size_t)(16 + ld_row) * 16 + ld_off);
        cp16(smem_u32(&Ks[0][(ld_row + 64) * PAD + ld_off]), Kg + (size_t)(80 + ld_row) * 16 + ld_off);
        cp16(smem_u32(&Vs[0][ld_row * PAD + ld_off]),        Vg + (size_t)(16 + ld_row) * 16 + ld_off);
        cp16(smem_u32(&Vs[0][(ld_row + 64) * PAD + ld_off]), Vg + (size_t)(80 + ld_row) * 16 + ld_off);
        asm volatile("cp.async.commit_group;");

        asm volatile("cp.async.wait_group 1;" ::: "memory");
        __syncthreads();

        uint32_t qa[4];
        ldm4(qa[0], qa[1], qa[2], qa[3], smem_u32(&Qs[qfrow * PAD + qfcol]));

        float m0, m1;
        float o[2][4] = {{0.f,0.f,0.f,0.f},{0.f,0.f,0.f,0.f}};
        float oL[4]   = {0.f,0.f,0.f,0.f};

        // ---- prologue: 16 keys, unmasked ----
        {
            float sc[2][4] = {{0.f,0.f,0.f,0.f},{0.f,0.f,0.f,0.f}};
            uint32_t b0, b1, b2, b3;
            ldm4(b0, b1, b2, b3, smem_u32(&K0s[krow * PAD + kcol]));
            {
                uint32_t bl[2] = { b0, b1 }, bh2[2] = { b2, b3 };
                mma16816(sc[0], qa, bl);
                mma16816(sc[1], qa, bh2);
            }
            float rm0 = fmaxf(fmaxf(sc[0][0], sc[0][1]), fmaxf(sc[1][0], sc[1][1]));
            float rm1 = fmaxf(fmaxf(sc[0][2], sc[0][3]), fmaxf(sc[1][2], sc[1][3]));
            rm0 = fmaxf(rm0, __shfl_xor_sync(0xffffffff, rm0, 1));
            rm0 = fmaxf(rm0, __shfl_xor_sync(0xffffffff, rm0, 2));
            rm1 = fmaxf(rm1, __shfl_xor_sync(0xffffffff, rm1, 1));
            rm1 = fmaxf(rm1, __shfl_xor_sync(0xffffffff, rm1, 2));
            m0 = rm0; m1 = rm1;

            uint32_t pa[4];
            pa[0] = ex2h2(sc[0][0] - m0, sc[0][1] - m0);
            pa[1] = ex2h2(sc[0][2] - m1, sc[0][3] - m1);
            pa[2] = ex2h2(sc[1][0] - m0, sc[1][1] - m0);
            pa[3] = ex2h2(sc[1][2] - m1, sc[1][3] - m1);

            uint32_t v0, v1, v2, v3;
            ldm4t(v0, v1, v2, v3, smem_u32(&V0s[vrow * PAD + vcol]));
            uint32_t bl[2] = { v0, v1 }, bh2[2] = { v2, v3 };
            mma16816(o[0], pa, bl);
            mma16816(o[1], pa, bh2);
            mma16816(oL,   pa, onesb);
        }

        const int jmax = (q0 + 63) >> 7;

        for (int jt = 0; jt <= jmax; jt++) {
            const int buf = jt & 1;
            if (jt < jmax) {
                const size_t kb = (size_t)(16 + (jt + 1) * 128);
                cp16(smem_u32(&Ks[buf ^ 1][ld_row * PAD + ld_off]),        Kg + (kb + ld_row) * 16 + ld_off);
                cp16(smem_u32(&Ks[buf ^ 1][(ld_row + 64) * PAD + ld_off]), Kg + (kb + ld_row + 64) * 16 + ld_off);
                cp16(smem_u32(&Vs[buf ^ 1][ld_row * PAD + ld_off]),        Vg + (kb + ld_row) * 16 + ld_off);
                cp16(smem_u32(&Vs[buf ^ 1][(ld_row + 64) * PAD + ld_off]), Vg + (kb + ld_row + 64) * 16 + ld_off);
                asm volatile("cp.async.commit_group;");
                asm volatile("cp.async.wait_group 1;" ::: "memory");
            } else {
                asm volatile("cp.async.wait_group 0;" ::: "memory");
            }
            __syncthreads();

            if (jt < jmax) {
                // ===== FULL TILE: 128 keys, single softmax update =====
                float sc[16][4];
#pragma unroll
                for (int nt = 0; nt < 16; nt++)
#pragma unroll
                    for (int tt = 0; tt < 4; tt++) sc[nt][tt] = 0.f;

#pragma unroll
                for (int i = 0; i < 8; i++) {
                    uint32_t b0, b1, b2, b3;
                    ldm4(b0, b1, b2, b3,
                         smem_u32(&Ks[buf][(16 * i + krow) * PAD + kcol]));
                    uint32_t bl[2] = { b0, b1 }, bh2[2] = { b2, b3 };
                    mma16816(sc[2 * i],     qa, bl);
                    mma16816(sc[2 * i + 1], qa, bh2);
                }

                // tree-structured row max (depth ~5 instead of 16)
                float p0[16], p1[16];
#pragma unroll
                for (int nt = 0; nt < 16; nt++) {
                    p0[nt] = fmaxf(sc[nt][0], sc[nt][1]);
                    p1[nt] = fmaxf(sc[nt][2], sc[nt][3]);
                }
#pragma unroll
                for (int st = 8; st >= 1; st >>= 1)
#pragma unroll
                    for (int k2 = 0; k2 < st; k2++) {
                        p0[k2] = fmaxf(p0[k2], p0[k2 + st]);
                        p1[k2] = fmaxf(p1[k2], p1[k2 + st]);
                    }
                float rm0 = p0[0], rm1 = p1[0];
                rm0 = fmaxf(rm0, __shfl_xor_sync(0xffffffff, rm0, 1));
                rm0 = fmaxf(rm0, __shfl_xor_sync(0xffffffff, rm0, 2));
                rm1 = fmaxf(rm1, __shfl_xor_sync(0xffffffff, rm1, 1));
                rm1 = fmaxf(rm1, __shfl_xor_sync(0xffffffff, rm1, 2));

                const float mn0 = fmaxf(m0, rm0);
                const float mn1 = fmaxf(m1, rm1);
                const float c0 = ex2f(m0 - mn0);
                const float c1 = ex2f(m1 - mn1);
                m0 = mn0; m1 = mn1;
                o[0][0] *= c0; o[0][1] *= c0; o[0][2] *= c1; o[0][3] *= c1;
                o[1][0] *= c0; o[1][1] *= c0; o[1][2] *= c1; o[1][3] *= c1;
                oL[0]   *= c0; oL[1]   *= c0; oL[2]   *= c1; oL[3]   *= c1;

#pragma unroll
                for (int kt = 0; kt < 8; kt++) {
                    uint32_t pa[4];
                    pa[0] = ex2h2(sc[2 * kt][0] - mn0,     sc[2 * kt][1] - mn0);
                    pa[1] = ex2h2(sc[2 * kt][2] - mn1,     sc[2 * kt][3] - mn1);
                    pa[2] = ex2h2(sc[2 * kt + 1][0] - mn0, sc[2 * kt + 1][1] - mn0);
                    pa[3] = ex2h2(sc[2 * kt + 1][2] - mn1, sc[2 * kt + 1][3] - mn1);
                    uint32_t v0, v1, v2, v3;
                    ldm4t(v0, v1, v2, v3,
                          smem_u32(&Vs[buf][(16 * kt + vrow) * PAD + vcol]));
                    uint32_t bl[2] = { v0, v1 }, bh2[2] = { v2, v3 };
                    mma16816(o[0], pa, bl);
                    mma16816(o[1], pa, bh2);
                    mma16816(oL,   pa, onesb);
                }
                __syncthreads();   // protect buf reuse by next prefetch
            } else {
                // ===== DIAG TILE: chunked + warp-uniform skips + mask =====
                const int off = q0 - 128 * jt;
                const int wb  = off + warp * 16 + 15;

#pragma unroll
                for (int c = 0; c < 2; c++) {
                    if (c * 64 <= wb) {
                        float sc[8][4];
#pragma unroll
                        for (int nt = 0; nt < 8; nt++)
#pragma unroll
                            for (int tt = 0; tt < 4; tt++) sc[nt][tt] = 0.f;

#pragma unroll
                        for (int i = 0; i < 4; i++) {
                            if ((c * 64 + i * 16) <= wb) {
                                uint32_t b0, b1, b2, b3;
                                ldm4(b0, b1, b2, b3,
                                     smem_u32(&Ks[buf][(16 * (c * 4 + i) + krow) * PAD + kcol]));
                                uint32_t bl[2] = { b0, b1 }, bh2[2] = { b2, b3 };
                                mma16816(sc[2 * i],     qa, bl);
                                mma16816(sc[2 * i + 1], qa, bh2);
                            }
                        }

                        {
                            const int jb = c * 64 + (lane & 3) * 2;
                            const int t0 = off + warp * 16 + (lane >> 2);
                            const int t1 = t0 + 8;
#pragma unroll
                            for (int nt = 0; nt < 8; nt++) {
                                int j0 = jb + nt * 8;
                                if (j0     > t0) sc[nt][0] = -1e30f;
                                if (j0 + 1 > t0) sc[nt][1] = -1e30f;
                                if (j0     > t1) sc[nt][2] = -1e30f;
                                if (j0 + 1 > t1) sc[nt][3] = -1e30f;
                            }
                        }

                        // tree max
                        float p0[8], p1[8];
#pragma unroll
                        for (int nt = 0; nt < 8; nt++) {
                            p0[nt] = fmaxf(sc[nt][0], sc[nt][1]);
                            p1[nt] = fmaxf(sc[nt][2], sc[nt][3]);
                        }
#pragma unroll
                        for (int st = 4; st >= 1; st >>= 1)
#pragma unroll
                            for (int k2 = 0; k2 < st; k2++) {
                                p0[k2] = fmaxf(p0[k2], p0[k2 + st]);
                                p1[k2] = fmaxf(p1[k2], p1[k2 + st]);
                            }
                        float rm0 = p0[0], rm1 = p1[0];
                        rm0 = fmaxf(rm0, __shfl_xor_sync(0xffffffff, rm0, 1));
                        rm0 = fmaxf(rm0, __shfl_xor_sync(0xffffffff, rm0, 2));
                        rm1 = fmaxf(rm1, __shfl_xor_sync(0xffffffff, rm1, 1));
                        rm1 = fmaxf(rm1, __shfl_xor_sync(0xffffffff, rm1, 2));

                        const float mn0 = fmaxf(m0, rm0);
                        const float mn1 = fmaxf(m1, rm1);
                        const float c0 = ex2f(m0 - mn0);
                        const float c1 = ex2f(m1 - mn1);
                        m0 = mn0; m1 = mn1;
                        o[0][0] *= c0; o[0][1] *= c0; o[0][2] *= c1; o[0][3] *= c1;
                        o[1][0] *= c0; o[1][1] *= c0; o[1][2] *= c1; o[1][3] *= c1;
                        oL[0]   *= c0; oL[1]   *= c0; oL[2]   *= c1; oL[3]   *= c1;

#pragma unroll
                        for (int kt = 0; kt < 4; kt++) {
                            if ((c * 64 + kt * 16) <= wb) {
                                uint32_t pa[4];
                                pa[0] = ex2h2(sc[2 * kt][0] - mn0,     sc[2 * kt][1] - mn0);
                                pa[1] = ex2h2(sc[2 * kt][2] - mn1,     sc[2 * kt][3] - mn1);
                                pa[2] = ex2h2(sc[2 * kt + 1][0] - mn0, sc[2 * kt + 1][1] - mn0);
                                pa[3] = ex2h2(sc[2 * kt + 1][2] - mn1, sc[2 * kt + 1][3] - mn1);
                                uint32_t v0, v1, v2, v3;
                                ldm4t(v0, v1, v2, v3,
                                      smem_u32(&Vs[buf][(16 * (c * 4 + kt) + vrow) * PAD + vcol]));
                                uint32_t bl[2] = { v0, v1 }, bh2[2] = { v2, v3 };
                                mma16816(o[0], pa, bl);
                                mma16816(o[1], pa, bh2);
                                mma16816(oL,   pa, onesb);
                            }
                        }
                    }
                }
                // no barrier after the final tile: the next pass starts with
                // __syncthreads() before any smem write, and kernel exit
                // needs none.
            }
        }

        const float inv0 = 1.f / oL[0];
        const float inv1 = 1.f / oL[2];

        const int qrow0 = q0 + warp * 16 + (lane >> 2);
        const int b = bh >> 4, h = bh & 15;
        const int col = (lane & 3) * 2;
#pragma unroll
        for (int vt = 0; vt < 2; vt++) {
            uint32_t lo = packh2(o[vt][0] * inv0, o[vt][1] * inv0);
            uint32_t hi = packh2(o[vt][2] * inv1, o[vt][3] * inv1);
            size_t base0 = ((size_t)(b * S_ + qrow0)     ) * NOV_ + h * 16 + vt * 8 + col;
            size_t base1 = ((size_t)(b * S_ + qrow0 + 8) ) * NOV_ + h * 16 + vt * 8 + col;
            *(uint32_t*)&g_Zh[base0] = lo;
            *(uint32_t*)&g_Zh[base1] = hi;
        }
    }
}

// ---------------------------------------------------------------------------
// Launch
// ---------------------------------------------------------------------------
extern "C" void kernel_launch(void* const* d_in, const int* in_sizes, int n_in,
                              void* d_out, int out_size)
{
    const float* resid = (const float*)d_in[0];
    const float* W_Q   = (const float*)d_in[1];
    const float* W_K   = (const float*)d_in[2];
    const float* W_V   = (const float*)d_in[3];
    const float* W_O   = (const float*)d_in[4];
    const float* b_Q   = (const float*)d_in[5];
    const float* b_K   = (const float*)d_in[6];
    const float* b_V   = (const float*)d_in[7];
    const float* b_O   = (const float*)d_in[8];
    const float* v_k   = (const float*)d_in[9];
    const float* v_v   = (const float*)d_in[10];
    float* out = (float*)d_out;

    __half *Ah, *Wh1, *Wh2, *Zh;
    cudaGetSymbolAddress((void**)&Ah,  g_Ah);
    cudaGetSymbolAddress((void**)&Wh1, g_Wh1);
    cudaGetSymbolAddress((void**)&Wh2, g_Wh2);
    cudaGetSymbolAddress((void**)&Zh,  g_Zh);

    cudaFuncSetAttribute(hgemm<0>, cudaFuncAttributeMaxDynamicSharedMemorySize, HG_SMEM_BYTES);
    cudaFuncSetAttribute(hgemm<1>, cudaFuncAttributeMaxDynamicSharedMemorySize, HG_SMEM_BYTES);

    // 1) fused prep
    prep_kernel<<<PREP_BLKS, 256>>>(W_Q, W_K, W_V, W_O, resid, v_k, v_v);

    // 2) GEMM1 + fused bias/rotary/scatter epilogue -> g_Qh/g_Kh/g_Vh
    {
        dim3 grid(DM_ / 128, BS_ / 64);
        hgemm<1><<<grid, 256, HG_SMEM_BYTES>>>(Ah, Wh1, nullptr, BS_, DM_, DM_,
                                               nullptr, b_Q, b_K, b_V);
    }

    // 3) tensor-core flash attention
    {
        dim3 grid(16, B_ * NQK_);
        attn_mma<<<grid, 128>>>();
    }

    // 4) GEMM2: (4096 x 768) = Zh * Wh2^T + b_O -> out fp32
    {
        dim3 grid(DM_ / 128, BS_ / 64);
        hgemm<0><<<grid, 256, HG_SMEM_BYTES>>>(Zh, Wh2, out, BS_, DM_, NOV_,
                                               b_O, nullptr, nullptr, nullptr);
    }
}

// round 14
// speedup vs baseline: 1.0716x; 1.0258x over previous
#include <cuda_runtime.h>
#include <cuda_fp16.h>
#include <cstdint>

// ---------------------------------------------------------------------------
// Problem constants
// ---------------------------------------------------------------------------
#define B_   2
#define S_   2048
#define DM_  768
#define NQK_ 16
#define DQK_ 16
#define NOV_ 256
#define VKV_ 16
#define SK_  (S_ + VKV_)     // 2064 keys = 16 + 16*128 (exact)
#define BS_  (B_ * S_)       // 4096 rows

// ---------------------------------------------------------------------------
// Device scratch
// ---------------------------------------------------------------------------
__device__ __half g_Ah  [BS_ * DM_];
__device__ __half g_Wh1 [DM_ * DM_];
__device__ __half g_Wh2 [DM_ * NOV_];
__device__ float  g_rot [S_ * 16];                  // [s][0..7]=sin, [8..15]=cos
__device__ __half g_Qh  [B_ * NQK_ * S_  * DQK_];
__device__ __half g_Kh  [B_ * NQK_ * SK_ * DQK_];
__device__ __half g_Vh  [B_ * NQK_ * SK_ * DQK_];
__device__ __half g_Zh  [BS_ * NOV_];

// ---------------------------------------------------------------------------
// helpers
// ---------------------------------------------------------------------------
__device__ __forceinline__ uint32_t smem_u32(const void* p) {
    return (uint32_t)__cvta_generic_to_shared(p);
}
__device__ __forceinline__ void cp16(uint32_t s, const void* g) {
    asm volatile("cp.async.cg.shared.global [%0], [%1], 16;" :: "r"(s), "l"(g));
}
__device__ __forceinline__ float ex2f(float x) {
    float y; asm("ex2.approx.ftz.f32 %0, %1;" : "=f"(y) : "f"(x)); return y;
}
__device__ __forceinline__ uint32_t ex2h2(float lo, float hi) {
    uint32_t h, r;
    asm("cvt.rn.f16x2.f32 %0, %1, %2;" : "=r"(h) : "f"(hi), "f"(lo));
    asm("ex2.approx.f16x2 %0, %1;" : "=r"(r) : "r"(h));
    return r;
}
__device__ __forceinline__ void ldm4(uint32_t& r0, uint32_t& r1, uint32_t& r2, uint32_t& r3, uint32_t addr) {
    asm volatile("ldmatrix.sync.aligned.m8n8.x4.shared.b16 {%0,%1,%2,%3}, [%4];"
                 : "=r"(r0), "=r"(r1), "=r"(r2), "=r"(r3) : "r"(addr));
}
__device__ __forceinline__ void ldm4t(uint32_t& r0, uint32_t& r1, uint32_t& r2, uint32_t& r3, uint32_t addr) {
    asm volatile("ldmatrix.sync.aligned.m8n8.x4.trans.shared.b16 {%0,%1,%2,%3}, [%4];"
                 : "=r"(r0), "=r"(r1), "=r"(r2), "=r"(r3) : "r"(addr));
}
__device__ __forceinline__ void mma16816(float* d, const uint32_t* a, const uint32_t* b) {
    asm volatile("mma.sync.aligned.m16n8k16.row.col.f32.f16.f16.f32 "
                 "{%0,%1,%2,%3},{%4,%5,%6,%7},{%8,%9},{%0,%1,%2,%3};"
                 : "+f"(d[0]), "+f"(d[1]), "+f"(d[2]), "+f"(d[3])
                 : "r"(a[0]), "r"(a[1]), "r"(a[2]), "r"(a[3]), "r"(b[0]), "r"(b[1]));
}
__device__ __forceinline__ uint32_t packh2(float x, float y) {
    __half2 h = __floats2half2_rn(x, y);
    return *(uint32_t*)&h;
}
// packed quad-reduction max of (rm0, rm1) via half2 (2 shfls instead of 4)
__device__ __forceinline__ void quadmax2(float& rm0, float& rm1) {
    __half2 hm = __floats2half2_rn(rm0, rm1);
    uint32_t u = *(uint32_t*)&hm;
    uint32_t v = __shfl_xor_sync(0xffffffff, u, 1);
    hm = __hmax2(hm, *(__half2*)&v);
    u = *(uint32_t*)&hm;
    v = __shfl_xor_sync(0xffffffff, u, 2);
    hm = __hmax2(hm, *(__half2*)&v);
    rm0 = __low2float(hm);
    rm1 = __high2float(hm);
}

#define QSCALE 0.36067376022224085f   // 0.25 * log2(e)

// ---------------------------------------------------------------------------
// 1) Fused prep (unchanged)
// ---------------------------------------------------------------------------
#define PREP_TQK0 0
#define PREP_V0   384
#define PREP_W20  1152
#define PREP_CV0  1344
#define PREP_RT0  4416
#define PREP_VV0  4480
#define PREP_BLKS 4512

__global__ void prep_kernel(const float* __restrict__ WQ,
                            const float* __restrict__ WK,
                            const float* __restrict__ WV,
                            const float* __restrict__ WO,
                            const float* __restrict__ resid,
                            const float* __restrict__ vk,
                            const float* __restrict__ vv)
{
    __shared__ float sm[64 * 17];
    const int blk = blockIdx.x;
    const int t = threadIdx.x;

    if (blk < PREP_V0) {
        int rem = blk, mat = rem / 192; rem %= 192;
        int h = rem / 12, d0 = (rem % 12) * 64;
        const float* W = mat ? WK : WQ;
        {
            int row = t >> 2, part = t & 3;
            float4 v = *(const float4*)&W[((size_t)h * DM_ + d0 + row) * DQK_ + part * 4];
            sm[row * 17 + part * 4 + 0] = v.x;
            sm[row * 17 + part * 4 + 1] = v.y;
            sm[row * 17 + part * 4 + 2] = v.z;
            sm[row * 17 + part * 4 + 3] = v.w;
        }
        __syncthreads();
        {
            int e = t >> 4, dcol = (t & 15) * 4;
            int c = mat * 256 + h * 16 + e;
            __half* dst = &g_Wh1[(size_t)c * DM_ + d0 + dcol];
            *(__half2*)&dst[0] = __floats2half2_rn(sm[(dcol + 0) * 17 + e], sm[(dcol + 1) * 17 + e]);
            *(__half2*)&dst[2] = __floats2half2_rn(sm[(dcol + 2) * 17 + e], sm[(dcol + 3) * 17 + e]);
        }
    } else if (blk < PREP_W20) {
        int idx = (blk - PREP_V0) * 256 + t;
        g_Wh1[512 * DM_ + idx] = __float2half(WV[idx]);
    } else if (blk < PREP_CV0) {
        int rem = blk - PREP_W20;
        int n0 = (rem / 12) * 16, m0 = (rem % 12) * 64;
        {
            int row = t >> 4, part = t & 15;
            float4 v = *(const float4*)&WO[(size_t)(n0 + row) * DM_ + m0 + part * 4];
            sm[row * 65 + part * 4 + 0] = v.x;
            sm[row * 65 + part * 4 + 1] = v.y;
            sm[row * 65 + part * 4 + 2] = v.z;
            sm[row * 65 + part * 4 + 3] = v.w;
        }
        __syncthreads();
        {
            int mm = t >> 2, nn = (t & 3) * 4;
            __half* dst = &g_Wh2[(size_t)(m0 + mm) * NOV_ + n0 + nn];
            *(__half2*)&dst[0] = __floats2half2_rn(sm[(nn + 0) * 65 + mm], sm[(nn + 1) * 65 + mm]);
            *(__half2*)&dst[2] = __floats2half2_rn(sm[(nn + 2) * 65 + mm], sm[(nn + 3) * 65 + mm]);
        }
    } else if (blk < PREP_RT0) {
        int i = ((blk - PREP_CV0) * 256 + t) * 4;
        float4 v = *(const float4*)(resid + i);
        *(__half2*)&g_Ah[i]     = __floats2half2_rn(v.x, v.y);
        *(__half2*)&g_Ah[i + 2] = __floats2half2_rn(v.z, v.w);
    } else if (blk < PREP_VV0) {
        int idx = (blk - PREP_RT0) * 256 + t;
        int s = idx >> 3, i = idx & 7;
        float freq = powf(10000.f, (float)i / 8.f);
        float sn, cs;
        sincosf((float)s / freq, &sn, &cs);
        g_rot[s * 16 + i]     = sn;
        g_rot[s * 16 + 8 + i] = cs;
    } else {
        int idx = (blk - PREP_VV0) * 256 + t;
        int c = idx & 255;
        int m = (idx >> 8) & 15;
        int b = idx >> 12;
        int h = c >> 4, e = c & 15;
        size_t row = ((size_t)(b * NQK_ + h) * SK_ + S_ + m) * DQK_ + e;
        g_Kh[row] = __float2half(vk[m * 256 + c]);
        g_Vh[row] = __float2half(vv[m * 256 + c]);
    }
}

// ---------------------------------------------------------------------------
// 2) fp16 tensor-core GEMM: 64x128 tile, 256 threads, 4-stage (R11 config)
// ---------------------------------------------------------------------------
#define BKH 32
#define LDT 40
#define HG_STAGES 4
#define HG_A_HALVES (64  * LDT)
#define HG_B_HALVES (128 * LDT)
#define HG_SMEM_BYTES (HG_STAGES * (HG_A_HALVES + HG_B_HALVES) * 2)

template<int MODE>
__global__ __launch_bounds__(256)
void hgemm(const __half* __restrict__ A, const __half* __restrict__ Bm,
           float* __restrict__ C, int M, int N, int K,
           const float* __restrict__ bias,
           const float* __restrict__ bQv,
           const float* __restrict__ bKv,
           const float* __restrict__ bVv)
{
    extern __shared__ __half smh[];
    __half* Asm = smh;
    __half* Bsm = smh + HG_STAGES * HG_A_HALVES;

    const int tid  = threadIdx.x;
    const int warp = tid >> 5, lane = tid & 31;
    const int wm = warp >> 2, wn = warp & 3;
    const int bm = blockIdx.y * 64, bn = blockIdx.x * 128;

    const int arow = tid >> 2;
    const int aoff = (tid & 3) * 8;
    const int brow = tid >> 1;
    const int boff = (tid & 1) * 16;

    const __half* Ag = A + (size_t)(bm + arow) * K + aoff;
    const __half* Bg = Bm + (size_t)(bn + brow) * K + boff;
    const uint32_t AsB = smem_u32(Asm);
    const uint32_t BsB = smem_u32(Bsm);
    const uint32_t stA = (uint32_t)(arow * LDT + aoff) * 2;
    const uint32_t stB = (uint32_t)(brow * LDT + boff) * 2;
    const uint32_t SA = HG_A_HALVES * 2;
    const uint32_t SB = HG_B_HALVES * 2;

    const int mat = lane >> 3, r = lane & 7;
    const uint32_t a_off = (uint32_t)((wm * 32 + (mat & 1) * 8 + r) * LDT + (mat >> 1) * 8) * 2;
    const uint32_t b_off = (uint32_t)((wn * 32 + (mat >> 1) * 8 + r) * LDT + (mat & 1) * 8) * 2;

    float acc[2][4][4];
#pragma unroll
    for (int i = 0; i < 2; i++)
#pragma unroll
        for (int j = 0; j < 4; j++)
#pragma unroll
            for (int tt = 0; tt < 4; tt++) acc[i][j][tt] = 0.f;

    const int KT = K / BKH;

#pragma unroll
    for (int s = 0; s < 3; s++) {
        cp16(AsB + s * SA + stA,      Ag + s * BKH);
        cp16(BsB + s * SB + stB,      Bg + s * BKH);
        cp16(BsB + s * SB + stB + 16, Bg + s * BKH + 8);
        asm volatile("cp.async.commit_group;");
    }
    asm volatile("cp.async.wait_group 2;" ::: "memory");
    __syncthreads();

    int stage = 0;
    for (int kt = 0; kt < KT; kt++) {
        const uint32_t Abuf = AsB + (uint32_t)stage * SA;
        const uint32_t Bbuf = BsB + (uint32_t)stage * SB;
#pragma unroll
        for (int ks = 0; ks < 2; ks++) {
            uint32_t a[2][4];
#pragma unroll
            for (int mt = 0; mt < 2; mt++)
                ldm4(a[mt][0], a[mt][1], a[mt][2], a[mt][3],
                     Abuf + a_off + (uint32_t)(mt * 16 * LDT + ks * 16) * 2);
            uint32_t bf[4][2];
#pragma unroll
            for (int p = 0; p < 2; p++) {
                uint32_t r0, r1, r2, r3;
                ldm4(r0, r1, r2, r3,
                     Bbuf + b_off + (uint32_t)(p * 16 * LDT + ks * 16) * 2);
                bf[2 * p][0] = r0; bf[2 * p][1] = r1;
                bf[2 * p + 1][0] = r2; bf[2 * p + 1][1] = r3;
            }
#pragma unroll
            for (int mt = 0; mt < 2; mt++)
#pragma unroll
                for (int nt = 0; nt < 4; nt++)
                    mma16816(acc[mt][nt], a[mt], bf[nt]);
        }

        if (kt + 3 < KT) {
            const int ns = (stage + 3 >= HG_STAGES) ? stage + 3 - HG_STAGES : stage + 3;
            const __half* ag = Ag + (kt + 3) * BKH;
            const __half* bg = Bg + (kt + 3) * BKH;
            cp16(AsB + (uint32_t)ns * SA + stA,      ag);
            cp16(BsB + (uint32_t)ns * SB + stB,      bg);
            cp16(BsB + (uint32_t)ns * SB + stB + 16, bg + 8);
            asm volatile("cp.async.commit_group;");
            asm volatile("cp.async.wait_group 2;" ::: "memory");
        } else {
            asm volatile("cp.async.wait_group 0;" ::: "memory");
        }
        __syncthreads();
        stage = (stage + 1 >= HG_STAGES) ? 0 : stage + 1;
    }

    if (MODE == 0) {
#pragma unroll
        for (int mt = 0; mt < 2; mt++) {
            const int r0 = bm + wm * 32 + mt * 16 + (lane >> 2);
#pragma unroll
            for (int nt = 0; nt < 4; nt++) {
                const int c0 = bn + wn * 32 + nt * 8 + (lane & 3) * 2;
                float b0 = bias[c0], b1 = bias[c0 + 1];
                float2 v01 = { acc[mt][nt][0] + b0, acc[mt][nt][1] + b1 };
                float2 v23 = { acc[mt][nt][2] + b0, acc[mt][nt][3] + b1 };
                *(float2*)(C + (size_t)r0 * N + c0)       = v01;
                *(float2*)(C + (size_t)(r0 + 8) * N + c0) = v23;
            }
        }
    } else {
        const int i = (lane & 3) * 2;
#pragma unroll
        for (int mt = 0; mt < 2; mt++) {
            const int r0 = bm + wm * 32 + mt * 16 + (lane >> 2);
#pragma unroll
            for (int rr = 0; rr < 2; rr++) {
                const int row = r0 + rr * 8;
                const int s = row & (S_ - 1);
                const int b = row >> 11;
                const float* rt = &g_rot[s * 16];
#pragma unroll
                for (int np = 0; np < 2; np++) {
                    const int base = bn + wn * 32 + np * 16;
                    const float vlo0 = acc[mt][2 * np][2 * rr + 0];
                    const float vlo1 = acc[mt][2 * np][2 * rr + 1];
                    const float vhi0 = acc[mt][2 * np + 1][2 * rr + 0];
                    const float vhi1 = acc[mt][2 * np + 1][2 * rr + 1];
                    if (base < 256) {
                        const int h = base >> 4;
                        float a0 = vlo0 + bQv[h * 16 + i];
                        float a1 = vlo1 + bQv[h * 16 + i + 1];
                        float c0 = vhi0 + bQv[h * 16 + i + 8];
                        float c1 = vhi1 + bQv[h * 16 + i + 9];
                        float sn0 = rt[i], sn1 = rt[i + 1];
                        float cs0 = rt[8 + i], cs1 = rt[9 + i];
                        __half* dst = &g_Qh[((size_t)(b * NQK_ + h) * S_ + s) * DQK_];
                        *(__half2*)&dst[i]     = __floats2half2_rn((a0 * cs0 - c0 * sn0) * QSCALE,
                                                                   (a1 * cs1 - c1 * sn1) * QSCALE);
                        *(__half2*)&dst[i + 8] = __floats2half2_rn((c0 * cs0 + a0 * sn0) * QSCALE,
                                                                   (c1 * cs1 + a1 * sn1) * QSCALE);
                    } else if (base < 512) {
                        const int h = (base - 256) >> 4;
                        float a0 = vlo0 + bKv[h * 16 + i];
                        float a1 = vlo1 + bKv[h * 16 + i + 1];
                        float c0 = vhi0 + bKv[h * 16 + i + 8];
                        float c1 = vhi1 + bKv[h * 16 + i + 9];
                        float sn0 = rt[i], sn1 = rt[i + 1];
                        float cs0 = rt[8 + i], cs1 = rt[9 + i];
                        __half* dst = &g_Kh[((size_t)(b * NQK_ + h) * SK_ + s) * DQK_];
                        *(__half2*)&dst[i]     = __floats2half2_rn(a0 * cs0 - c0 * sn0,
                                                                   a1 * cs1 - c1 * sn1);
                        *(__half2*)&dst[i + 8] = __floats2half2_rn(c0 * cs0 + a0 * sn0,
                                                                   c1 * cs1 + a1 * sn1);
                    } else {
                        const int n0 = base - 512;
                        const int h = n0 >> 4;
                        __half* dst = &g_Vh[((size_t)(b * NQK_ + h) * SK_ + s) * DQK_];
                        *(__half2*)&dst[i]     = __floats2half2_rn(vlo0 + bVv[n0 + i],
                                                                   vlo1 + bVv[n0 + i + 1]);
                        *(__half2*)&dst[i + 8] = __floats2half2_rn(vhi0 + bVv[n0 + i + 8],
                                                                   vhi1 + bVv[n0 + i + 9]);
                    }
                }
            }
        }
    }
}

// ---------------------------------------------------------------------------
// 3) Flash attention (R11 exact + packed quad-max + no final-tile barrier)
// ---------------------------------------------------------------------------
#define PAD 24

__global__ __launch_bounds__(128, 5)
void attn_mma()
{
    const int bh   = blockIdx.y;
    const int pp   = blockIdx.x;          // 0..15
    const int tid  = threadIdx.x;
    const int warp = tid >> 5, lane = tid & 31;

    __shared__ __half Qs[64 * PAD];
    __shared__ __half K0s[16 * PAD];
    __shared__ __half V0s[16 * PAD];
    __shared__ __half Ks[2][128 * PAD];
    __shared__ __half Vs[2][128 * PAD];

    const __half* Kg = g_Kh + (size_t)bh * SK_ * DQK_;
    const __half* Vg = g_Vh + (size_t)bh * SK_ * DQK_;

    const int ld_row = tid >> 1;
    const int ld_off = (tid & 1) * 8;

    if (tid < 32) {
        int pr = tid >> 1, po = (tid & 1) * 8;
        cp16(smem_u32(&K0s[pr * PAD + po]), Kg + (size_t)pr * 16 + po);
        cp16(smem_u32(&V0s[pr * PAD + po]), Vg + (size_t)pr * 16 + po);
    }
    asm volatile("cp.async.commit_group;");

    const int g = lane >> 3, r = lane & 7;
    const int qfrow = warp * 16 + (g & 1) * 8 + r;
    const int qfcol = (g >> 1) * 8;
    const int krow = (g >> 1) * 8 + r;
    const int kcol = (g & 1) * 8;
    const int vrow = (g & 1) * 8 + r;
    const int vcol = (g >> 1) * 8;
    const uint32_t onesb[2] = { 0x3C003C00u, 0x3C003C00u };

#pragma unroll 1
    for (int sel = 0; sel < 2; sel++) {
        const int qt = sel ? pp : (31 - pp);
        const int q0 = qt * 64;
        const __half* Qg = g_Qh + ((size_t)bh * S_ + q0) * DQK_;

        __syncthreads();

        *(float4*)&Qs[ld_row * PAD + ld_off] =
            *(const float4*)&Qg[(size_t)ld_row * 16 + ld_off];

        cp16(smem_u32(&Ks[0][ld_row * PAD + ld_off]),        Kg + (size_t)(16 + ld_row) * 16 + ld_off);
        cp16(smem_u32(&Ks[0][(ld_row + 64) * PAD + ld_off]), Kg + (size_t)(80 + ld_row) * 16 + ld_off);
        cp16(smem_u32(&Vs[0][ld_row * PAD + ld_off]),        Vg + (size_t)(16 + ld_row) * 16 + ld_off);
        cp16(smem_u32(&Vs[0][(ld_row + 64) * PAD + ld_off]), Vg + (size_t)(80 + ld_row) * 16 + ld_off);
        asm volatile("cp.async.commit_group;");

        asm volatile("cp.async.wait_group 1;" ::: "memory");
        __syncthreads();

        uint32_t qa[4];
        ldm4(qa[0], qa[1], qa[2], qa[3], smem_u32(&Qs[qfrow * PAD + qfcol]));

        float m0, m1;
        float o[2][4] = {{0.f,0.f,0.f,0.f},{0.f,0.f,0.f,0.f}};
        float oL[4]   = {0.f,0.f,0.f,0.f};

        // ---- prologue: 16 keys, unmasked ----
        {
            float sc[2][4] = {{0.f,0.f,0.f,0.f},{0.f,0.f,0.f,0.f}};
            uint32_t b0, b1, b2, b3;
            ldm4(b0, b1, b2, b3, smem_u32(&K0s[krow * PAD + kcol]));
            {
                uint32_t bl[2] = { b0, b1 }, bh2[2] = { b2, b3 };
                mma16816(sc[0], qa, bl);
                mma16816(sc[1], qa, bh2);
            }
            float rm0 = fmaxf(fmaxf(sc[0][0], sc[0][1]), fmaxf(sc[1][0], sc[1][1]));
            float rm1 = fmaxf(fmaxf(sc[0][2], sc[0][3]), fmaxf(sc[1][2], sc[1][3]));
            quadmax2(rm0, rm1);
            m0 = rm0; m1 = rm1;

            uint32_t pa[4];
            pa[0] = ex2h2(sc[0][0] - m0, sc[0][1] - m0);
            pa[1] = ex2h2(sc[0][2] - m1, sc[0][3] - m1);
            pa[2] = ex2h2(sc[1][0] - m0, sc[1][1] - m0);
            pa[3] = ex2h2(sc[1][2] - m1, sc[1][3] - m1);

            uint32_t v0, v1, v2, v3;
            ldm4t(v0, v1, v2, v3, smem_u32(&V0s[vrow * PAD + vcol]));
            uint32_t bl[2] = { v0, v1 }, bh2[2] = { v2, v3 };
            mma16816(o[0], pa, bl);
            mma16816(o[1], pa, bh2);
            mma16816(oL,   pa, onesb);
        }

        const int jmax = (q0 + 63) >> 7;

        for (int jt = 0; jt <= jmax; jt++) {
            const int buf = jt & 1;
            if (jt < jmax) {
                const size_t kb = (size_t)(16 + (jt + 1) * 128);
                cp16(smem_u32(&Ks[buf ^ 1][ld_row * PAD + ld_off]),        Kg + (kb + ld_row) * 16 + ld_off);
                cp16(smem_u32(&Ks[buf ^ 1][(ld_row + 64) * PAD + ld_off]), Kg + (kb + ld_row + 64) * 16 + ld_off);
                cp16(smem_u32(&Vs[buf ^ 1][ld_row * PAD + ld_off]),        Vg + (kb + ld_row) * 16 + ld_off);
                cp16(smem_u32(&Vs[buf ^ 1][(ld_row + 64) * PAD + ld_off]), Vg + (kb + ld_row + 64) * 16 + ld_off);
                asm volatile("cp.async.commit_group;");
                asm volatile("cp.async.wait_group 1;" ::: "memory");
            } else {
                asm volatile("cp.async.wait_group 0;" ::: "memory");
            }
            __syncthreads();

            if (jt < jmax) {
                // ===== FULL TILE: 128 keys, single softmax update =====
                float sc[16][4];
#pragma unroll
                for (int nt = 0; nt < 16; nt++)
#pragma unroll
                    for (int tt = 0; tt < 4; tt++) sc[nt][tt] = 0.f;

#pragma unroll
                for (int i = 0; i < 8; i++) {
                    uint32_t b0, b1, b2, b3;
                    ldm4(b0, b1, b2, b3,
                         smem_u32(&Ks[buf][(16 * i + krow) * PAD + kcol]));
                    uint32_t bl[2] = { b0, b1 }, bh2[2] = { b2, b3 };
                    mma16816(sc[2 * i],     qa, bl);
                    mma16816(sc[2 * i + 1], qa, bh2);
                }

                float rm0 = sc[0][0], rm1 = sc[0][2];
#pragma unroll
                for (int nt = 0; nt < 16; nt++) {
                    rm0 = fmaxf(rm0, fmaxf(sc[nt][0], sc[nt][1]));
                    rm1 = fmaxf(rm1, fmaxf(sc[nt][2], sc[nt][3]));
                }
                quadmax2(rm0, rm1);

                const float mn0 = fmaxf(m0, rm0);
                const float mn1 = fmaxf(m1, rm1);
                const float c0 = ex2f(m0 - mn0);
                const float c1 = ex2f(m1 - mn1);
                m0 = mn0; m1 = mn1;
                o[0][0] *= c0; o[0][1] *= c0; o[0][2] *= c1; o[0][3] *= c1;
                o[1][0] *= c0; o[1][1] *= c0; o[1][2] *= c1; o[1][3] *= c1;
                oL[0]   *= c0; oL[1]   *= c0; oL[2]   *= c1; oL[3]   *= c1;

#pragma unroll
                for (int kt = 0; kt < 8; kt++) {
                    uint32_t pa[4];
                    pa[0] = ex2h2(sc[2 * kt][0] - mn0,     sc[2 * kt][1] - mn0);
                    pa[1] = ex2h2(sc[2 * kt][2] - mn1,     sc[2 * kt][3] - mn1);
                    pa[2] = ex2h2(sc[2 * kt + 1][0] - mn0, sc[2 * kt + 1][1] - mn0);
                    pa[3] = ex2h2(sc[2 * kt + 1][2] - mn1, sc[2 * kt + 1][3] - mn1);
                    uint32_t v0, v1, v2, v3;
                    ldm4t(v0, v1, v2, v3,
                          smem_u32(&Vs[buf][(16 * kt + vrow) * PAD + vcol]));
                    uint32_t bl[2] = { v0, v1 }, bh2[2] = { v2, v3 };
                    mma16816(o[0], pa, bl);
                    mma16816(o[1], pa, bh2);
                    mma16816(oL,   pa, onesb);
                }
                __syncthreads();   // protect buf reuse by next prefetch
            } else {
                // ===== DIAG TILE: chunked + warp-uniform skips + mask =====
                const int off = q0 - 128 * jt;
                const int wb  = off + warp * 16 + 15;

#pragma unroll
                for (int c = 0; c < 2; c++) {
                    if (c * 64 <= wb) {
                        float sc[8][4];
#pragma unroll
                        for (int nt = 0; nt < 8; nt++)
#pragma unroll
                            for (int tt = 0; tt < 4; tt++) sc[nt][tt] = 0.f;

#pragma unroll
                        for (int i = 0; i < 4; i++) {
                            if ((c * 64 + i * 16) <= wb) {
                                uint32_t b0, b1, b2, b3;
                                ldm4(b0, b1, b2, b3,
                                     smem_u32(&Ks[buf][(16 * (c * 4 + i) + krow) * PAD + kcol]));
                                uint32_t bl[2] = { b0, b1 }, bh2[2] = { b2, b3 };
                                mma16816(sc[2 * i],     qa, bl);
                                mma16816(sc[2 * i + 1], qa, bh2);
                            }
                        }

                        {
                            const int jb = c * 64 + (lane & 3) * 2;
                            const int t0 = off + warp * 16 + (lane >> 2);
                            const int t1 = t0 + 8;
#pragma unroll
                            for (int nt = 0; nt < 8; nt++) {
                                int j0 = jb + nt * 8;
                                if (j0     > t0) sc[nt][0] = -1e30f;
                                if (j0 + 1 > t0) sc[nt][1] = -1e30f;
                                if (j0     > t1) sc[nt][2] = -1e30f;
                                if (j0 + 1 > t1) sc[nt][3] = -1e30f;
                            }
                        }

                        float rm0 = sc[0][0], rm1 = sc[0][2];
#pragma unroll
                        for (int nt = 0; nt < 8; nt++) {
                            rm0 = fmaxf(rm0, fmaxf(sc[nt][0], sc[nt][1]));
                            rm1 = fmaxf(rm1, fmaxf(sc[nt][2], sc[nt][3]));
                        }
                        quadmax2(rm0, rm1);

                        const float mn0 = fmaxf(m0, rm0);
                        const float mn1 = fmaxf(m1, rm1);
                        const float c0 = ex2f(m0 - mn0);
                        const float c1 = ex2f(m1 - mn1);
                        m0 = mn0; m1 = mn1;
                        o[0][0] *= c0; o[0][1] *= c0; o[0][2] *= c1; o[0][3] *= c1;
                        o[1][0] *= c0; o[1][1] *= c0; o[1][2] *= c1; o[1][3] *= c1;
                        oL[0]   *= c0; oL[1]   *= c0; oL[2]   *= c1; oL[3]   *= c1;

#pragma unroll
                        for (int kt = 0; kt < 4; kt++) {
                            if ((c * 64 + kt * 16) <= wb) {
                                uint32_t pa[4];
                                pa[0] = ex2h2(sc[2 * kt][0] - mn0,     sc[2 * kt][1] - mn0);
                                pa[1] = ex2h2(sc[2 * kt][2] - mn1,     sc[2 * kt][3] - mn1);
                                pa[2] = ex2h2(sc[2 * kt + 1][0] - mn0, sc[2 * kt + 1][1] - mn0);
                                pa[3] = ex2h2(sc[2 * kt + 1][2] - mn1, sc[2 * kt + 1][3] - mn1);
                                uint32_t v0, v1, v2, v3;
                                ldm4t(v0, v1, v2, v3,
                                      smem_u32(&Vs[buf][(16 * (c * 4 + kt) + vrow) * PAD + vcol]));
                                uint32_t bl[2] = { v0, v1 }, bh2[2] = { v2, v3 };
                                mma16816(o[0], pa, bl);
                                mma16816(o[1], pa, bh2);
                                mma16816(oL,   pa, onesb);
                            }
                        }
                    }
                }
                // no barrier after the final tile: next pass starts with
                // __syncthreads() before any smem write; kernel exit needs none.
            }
        }

        const float inv0 = 1.f / oL[0];
        const float inv1 = 1.f / oL[2];

        const int qrow0 = q0 + warp * 16 + (lane >> 2);
        const int b = bh >> 4, h = bh & 15;
        const int col = (lane & 3) * 2;
#pragma unroll
        for (int vt = 0; vt < 2; vt++) {
            uint32_t lo = packh2(o[vt][0] * inv0, o[vt][1] * inv0);
            uint32_t hi = packh2(o[vt][2] * inv1, o[vt][3] * inv1);
            size_t base0 = ((size_t)(b * S_ + qrow0)     ) * NOV_ + h * 16 + vt * 8 + col;
            size_t base1 = ((size_t)(b * S_ + qrow0 + 8) ) * NOV_ + h * 16 + vt * 8 + col;
            *(uint32_t*)&g_Zh[base0] = lo;
            *(uint32_t*)&g_Zh[base1] = hi;
        }
    }
}

// ---------------------------------------------------------------------------
// Launch
// ---------------------------------------------------------------------------
extern "C" void kernel_launch(void* const* d_in, const int* in_sizes, int n_in,
                              void* d_out, int out_size)
{
    const float* resid = (const float*)d_in[0];
    const float* W_Q   = (const float*)d_in[1];
    const float* W_K   = (const float*)d_in[2];
    const float* W_V   = (const float*)d_in[3];
    const float* W_O   = (const float*)d_in[4];
    const float* b_Q   = (const float*)d_in[5];
    const float* b_K   = (const float*)d_in[6];
    const float* b_V   = (const float*)d_in[7];
    const float* b_O   = (const float*)d_in[8];
    const float* v_k   = (const float*)d_in[9];
    const float* v_v   = (const float*)d_in[10];
    float* out = (float*)d_out;

    __half *Ah, *Wh1, *Wh2, *Zh;
    cudaGetSymbolAddress((void**)&Ah,  g_Ah);
    cudaGetSymbolAddress((void**)&Wh1, g_Wh1);
    cudaGetSymbolAddress((void**)&Wh2, g_Wh2);
    cudaGetSymbolAddress((void**)&Zh,  g_Zh);

    cudaFuncSetAttribute(hgemm<0>, cudaFuncAttributeMaxDynamicSharedMemorySize, HG_SMEM_BYTES);
    cudaFuncSetAttribute(hgemm<1>, cudaFuncAttributeMaxDynamicSharedMemorySize, HG_SMEM_BYTES);

    // 1) fused prep
    prep_kernel<<<PREP_BLKS, 256>>>(W_Q, W_K, W_V, W_O, resid, v_k, v_v);

    // 2) GEMM1 + fused bias/rotary/scatter epilogue -> g_Qh/g_Kh/g_Vh
    {
        dim3 grid(DM_ / 128, BS_ / 64);
        hgemm<1><<<grid, 256, HG_SMEM_BYTES>>>(Ah, Wh1, nullptr, BS_, DM_, DM_,
                                               nullptr, b_Q, b_K, b_V);
    }

    // 3) tensor-core flash attention
    {
        dim3 grid(16, B_ * NQK_);
        attn_mma<<<grid, 128>>>();
    }

    // 4) GEMM2: (4096 x 768) = Zh * Wh2^T + b_O -> out fp32
    {
        dim3 grid(DM_ / 128, BS_ / 64);
        hgemm<0><<<grid, 256, HG_SMEM_BYTES>>>(Zh, Wh2, out, BS_, DM_, NOV_,
                                               b_O, nullptr, nullptr, nullptr);
    }
}

// round 15
// speedup vs baseline: 1.0971x; 1.0238x over previous
#include <cuda_runtime.h>
#include <cuda_fp16.h>
#include <cstdint>

// ---------------------------------------------------------------------------
// Problem constants
// ---------------------------------------------------------------------------
#define B_   2
#define S_   2048
#define DM_  768
#define NQK_ 16
#define DQK_ 16
#define NOV_ 256
#define VKV_ 16
#define SK_  (S_ + VKV_)     // 2064 keys = 16 + 16*128 (exact)
#define BS_  (B_ * S_)       // 4096 rows

// ---------------------------------------------------------------------------
// Device scratch
// ---------------------------------------------------------------------------
__device__ __half g_Ah  [BS_ * DM_];
__device__ __half g_Wh1 [DM_ * DM_];
__device__ __half g_Wh2 [DM_ * NOV_];
__device__ float  g_rot [S_ * 16];                  // [s][0..7]=sin, [8..15]=cos
__device__ __half g_Qh  [B_ * NQK_ * S_  * DQK_];
__device__ __half g_Kh  [B_ * NQK_ * SK_ * DQK_];
__device__ __half g_Vh  [B_ * NQK_ * SK_ * DQK_];
__device__ __half g_Zh  [BS_ * NOV_];

// ---------------------------------------------------------------------------
// helpers
// ---------------------------------------------------------------------------
__device__ __forceinline__ void grid_dep_sync() {
#if __CUDA_ARCH__ >= 900
    cudaGridDependencySynchronize();
#endif
}
__device__ __forceinline__ uint32_t smem_u32(const void* p) {
    return (uint32_t)__cvta_generic_to_shared(p);
}
__device__ __forceinline__ void cp16(uint32_t s, const void* g) {
    asm volatile("cp.async.cg.shared.global [%0], [%1], 16;" :: "r"(s), "l"(g));
}
__device__ __forceinline__ float ex2f(float x) {
    float y; asm("ex2.approx.ftz.f32 %0, %1;" : "=f"(y) : "f"(x)); return y;
}
__device__ __forceinline__ uint32_t ex2h2(float lo, float hi) {
    uint32_t h, r;
    asm("cvt.rn.f16x2.f32 %0, %1, %2;" : "=r"(h) : "f"(hi), "f"(lo));
    asm("ex2.approx.f16x2 %0, %1;" : "=r"(r) : "r"(h));
    return r;
}
__device__ __forceinline__ void ldm4(uint32_t& r0, uint32_t& r1, uint32_t& r2, uint32_t& r3, uint32_t addr) {
    asm volatile("ldmatrix.sync.aligned.m8n8.x4.shared.b16 {%0,%1,%2,%3}, [%4];"
                 : "=r"(r0), "=r"(r1), "=r"(r2), "=r"(r3) : "r"(addr));
}
__device__ __forceinline__ void ldm4t(uint32_t& r0, uint32_t& r1, uint32_t& r2, uint32_t& r3, uint32_t addr) {
    asm volatile("ldmatrix.sync.aligned.m8n8.x4.trans.shared.b16 {%0,%1,%2,%3}, [%4];"
                 : "=r"(r0), "=r"(r1), "=r"(r2), "=r"(r3) : "r"(addr));
}
__device__ __forceinline__ void mma16816(float* d, const uint32_t* a, const uint32_t* b) {
    asm volatile("mma.sync.aligned.m16n8k16.row.col.f32.f16.f16.f32 "
                 "{%0,%1,%2,%3},{%4,%5,%6,%7},{%8,%9},{%0,%1,%2,%3};"
                 : "+f"(d[0]), "+f"(d[1]), "+f"(d[2]), "+f"(d[3])
                 : "r"(a[0]), "r"(a[1]), "r"(a[2]), "r"(a[3]), "r"(b[0]), "r"(b[1]));
}
__device__ __forceinline__ uint32_t packh2(float x, float y) {
    __half2 h = __floats2half2_rn(x, y);
    return *(uint32_t*)&h;
}

#define QSCALE 0.36067376022224085f   // 0.25 * log2(e)

// ---------------------------------------------------------------------------
// 1) Fused prep (unchanged)
// ---------------------------------------------------------------------------
#define PREP_TQK0 0
#define PREP_V0   384
#define PREP_W20  1152
#define PREP_CV0  1344
#define PREP_RT0  4416
#define PREP_VV0  4480
#define PREP_BLKS 4512

__global__ void prep_kernel(const float* __restrict__ WQ,
                            const float* __restrict__ WK,
                            const float* __restrict__ WV,
                            const float* __restrict__ WO,
                            const float* __restrict__ resid,
                            const float* __restrict__ vk,
                            const float* __restrict__ vv)
{
    __shared__ float sm[64 * 17];
    const int blk = blockIdx.x;
    const int t = threadIdx.x;

    if (blk < PREP_V0) {
        int rem = blk, mat = rem / 192; rem %= 192;
        int h = rem / 12, d0 = (rem % 12) * 64;
        const float* W = mat ? WK : WQ;
        {
            int row = t >> 2, part = t & 3;
            float4 v = *(const float4*)&W[((size_t)h * DM_ + d0 + row) * DQK_ + part * 4];
            sm[row * 17 + part * 4 + 0] = v.x;
            sm[row * 17 + part * 4 + 1] = v.y;
            sm[row * 17 + part * 4 + 2] = v.z;
            sm[row * 17 + part * 4 + 3] = v.w;
        }
        __syncthreads();
        {
            int e = t >> 4, dcol = (t & 15) * 4;
            int c = mat * 256 + h * 16 + e;
            __half* dst = &g_Wh1[(size_t)c * DM_ + d0 + dcol];
            *(__half2*)&dst[0] = __floats2half2_rn(sm[(dcol + 0) * 17 + e], sm[(dcol + 1) * 17 + e]);
            *(__half2*)&dst[2] = __floats2half2_rn(sm[(dcol + 2) * 17 + e], sm[(dcol + 3) * 17 + e]);
        }
    } else if (blk < PREP_W20) {
        int idx = (blk - PREP_V0) * 256 + t;
        g_Wh1[512 * DM_ + idx] = __float2half(WV[idx]);
    } else if (blk < PREP_CV0) {
        int rem = blk - PREP_W20;
        int n0 = (rem / 12) * 16, m0 = (rem % 12) * 64;
        {
            int row = t >> 4, part = t & 15;
            float4 v = *(const float4*)&WO[(size_t)(n0 + row) * DM_ + m0 + part * 4];
            sm[row * 65 + part * 4 + 0] = v.x;
            sm[row * 65 + part * 4 + 1] = v.y;
            sm[row * 65 + part * 4 + 2] = v.z;
            sm[row * 65 + part * 4 + 3] = v.w;
        }
        __syncthreads();
        {
            int mm = t >> 2, nn = (t & 3) * 4;
            __half* dst = &g_Wh2[(size_t)(m0 + mm) * NOV_ + n0 + nn];
            *(__half2*)&dst[0] = __floats2half2_rn(sm[(nn + 0) * 65 + mm], sm[(nn + 1) * 65 + mm]);
            *(__half2*)&dst[2] = __floats2half2_rn(sm[(nn + 2) * 65 + mm], sm[(nn + 3) * 65 + mm]);
        }
    } else if (blk < PREP_RT0) {
        int i = ((blk - PREP_CV0) * 256 + t) * 4;
        float4 v = *(const float4*)(resid + i);
        *(__half2*)&g_Ah[i]     = __floats2half2_rn(v.x, v.y);
        *(__half2*)&g_Ah[i + 2] = __floats2half2_rn(v.z, v.w);
    } else if (blk < PREP_VV0) {
        int idx = (blk - PREP_RT0) * 256 + t;
        int s = idx >> 3, i = idx & 7;
        float freq = powf(10000.f, (float)i / 8.f);
        float sn, cs;
        sincosf((float)s / freq, &sn, &cs);
        g_rot[s * 16 + i]     = sn;
        g_rot[s * 16 + 8 + i] = cs;
    } else {
        int idx = (blk - PREP_VV0) * 256 + t;
        int c = idx & 255;
        int m = (idx >> 8) & 15;
        int b = idx >> 12;
        int h = c >> 4, e = c & 15;
        size_t row = ((size_t)(b * NQK_ + h) * SK_ + S_ + m) * DQK_ + e;
        g_Kh[row] = __float2half(vk[m * 256 + c]);
        g_Vh[row] = __float2half(vv[m * 256 + c]);
    }
}

// ---------------------------------------------------------------------------
// 2) fp16 tensor-core GEMM: 64x128 tile, 256 threads, 4-stage (R11 config)
// ---------------------------------------------------------------------------
#define BKH 32
#define LDT 40
#define HG_STAGES 4
#define HG_A_HALVES (64  * LDT)
#define HG_B_HALVES (128 * LDT)
#define HG_SMEM_BYTES (HG_STAGES * (HG_A_HALVES + HG_B_HALVES) * 2)

template<int MODE>
__global__ __launch_bounds__(256)
void hgemm(const __half* __restrict__ A, const __half* __restrict__ Bm,
           float* __restrict__ C, int M, int N, int K,
           const float* __restrict__ bias,
           const float* __restrict__ bQv,
           const float* __restrict__ bKv,
           const float* __restrict__ bVv)
{
    grid_dep_sync();   // PDL: wait for producer kernel's data

    extern __shared__ __half smh[];
    __half* Asm = smh;
    __half* Bsm = smh + HG_STAGES * HG_A_HALVES;

    const int tid  = threadIdx.x;
    const int warp = tid >> 5, lane = tid & 31;
    const int wm = warp >> 2, wn = warp & 3;
    const int bm = blockIdx.y * 64, bn = blockIdx.x * 128;

    const int arow = tid >> 2;
    const int aoff = (tid & 3) * 8;
    const int brow = tid >> 1;
    const int boff = (tid & 1) * 16;

    const __half* Ag = A + (size_t)(bm + arow) * K + aoff;
    const __half* Bg = Bm + (size_t)(bn + brow) * K + boff;
    const uint32_t AsB = smem_u32(Asm);
    const uint32_t BsB = smem_u32(Bsm);
    const uint32_t stA = (uint32_t)(arow * LDT + aoff) * 2;
    const uint32_t stB = (uint32_t)(brow * LDT + boff) * 2;
    const uint32_t SA = HG_A_HALVES * 2;
    const uint32_t SB = HG_B_HALVES * 2;

    const int mat = lane >> 3, r = lane & 7;
    const uint32_t a_off = (uint32_t)((wm * 32 + (mat & 1) * 8 + r) * LDT + (mat >> 1) * 8) * 2;
    const uint32_t b_off = (uint32_t)((wn * 32 + (mat >> 1) * 8 + r) * LDT + (mat & 1) * 8) * 2;

    float acc[2][4][4];
#pragma unroll
    for (int i = 0; i < 2; i++)
#pragma unroll
        for (int j = 0; j < 4; j++)
#pragma unroll
            for (int tt = 0; tt < 4; tt++) acc[i][j][tt] = 0.f;

    const int KT = K / BKH;

#pragma unroll
    for (int s = 0; s < 3; s++) {
        cp16(AsB + s * SA + stA,      Ag + s * BKH);
        cp16(BsB + s * SB + stB,      Bg + s * BKH);
        cp16(BsB + s * SB + stB + 16, Bg + s * BKH + 8);
        asm volatile("cp.async.commit_group;");
    }
    asm volatile("cp.async.wait_group 2;" ::: "memory");
    __syncthreads();

    int stage = 0;
    for (int kt = 0; kt < KT; kt++) {
        const uint32_t Abuf = AsB + (uint32_t)stage * SA;
        const uint32_t Bbuf = BsB + (uint32_t)stage * SB;
#pragma unroll
        for (int ks = 0; ks < 2; ks++) {
            uint32_t a[2][4];
#pragma unroll
            for (int mt = 0; mt < 2; mt++)
                ldm4(a[mt][0], a[mt][1], a[mt][2], a[mt][3],
                     Abuf + a_off + (uint32_t)(mt * 16 * LDT + ks * 16) * 2);
            uint32_t bf[4][2];
#pragma unroll
            for (int p = 0; p < 2; p++) {
                uint32_t r0, r1, r2, r3;
                ldm4(r0, r1, r2, r3,
                     Bbuf + b_off + (uint32_t)(p * 16 * LDT + ks * 16) * 2);
                bf[2 * p][0] = r0; bf[2 * p][1] = r1;
                bf[2 * p + 1][0] = r2; bf[2 * p + 1][1] = r3;
            }
#pragma unroll
            for (int mt = 0; mt < 2; mt++)
#pragma unroll
                for (int nt = 0; nt < 4; nt++)
                    mma16816(acc[mt][nt], a[mt], bf[nt]);
        }

        if (kt + 3 < KT) {
            const int ns = (stage + 3 >= HG_STAGES) ? stage + 3 - HG_STAGES : stage + 3;
            const __half* ag = Ag + (kt + 3) * BKH;
            const __half* bg = Bg + (kt + 3) * BKH;
            cp16(AsB + (uint32_t)ns * SA + stA,      ag);
            cp16(BsB + (uint32_t)ns * SB + stB,      bg);
            cp16(BsB + (uint32_t)ns * SB + stB + 16, bg + 8);
            asm volatile("cp.async.commit_group;");
            asm volatile("cp.async.wait_group 2;" ::: "memory");
        } else {
            asm volatile("cp.async.wait_group 0;" ::: "memory");
        }
        __syncthreads();
        stage = (stage + 1 >= HG_STAGES) ? 0 : stage + 1;
    }

    if (MODE == 0) {
#pragma unroll
        for (int mt = 0; mt < 2; mt++) {
            const int r0 = bm + wm * 32 + mt * 16 + (lane >> 2);
#pragma unroll
            for (int nt = 0; nt < 4; nt++) {
                const int c0 = bn + wn * 32 + nt * 8 + (lane & 3) * 2;
                float b0 = bias[c0], b1 = bias[c0 + 1];
                float2 v01 = { acc[mt][nt][0] + b0, acc[mt][nt][1] + b1 };
                float2 v23 = { acc[mt][nt][2] + b0, acc[mt][nt][3] + b1 };
                *(float2*)(C + (size_t)r0 * N + c0)       = v01;
                *(float2*)(C + (size_t)(r0 + 8) * N + c0) = v23;
            }
        }
    } else {
        const int i = (lane & 3) * 2;
#pragma unroll
        for (int mt = 0; mt < 2; mt++) {
            const int r0 = bm + wm * 32 + mt * 16 + (lane >> 2);
#pragma unroll
            for (int rr = 0; rr < 2; rr++) {
                const int row = r0 + rr * 8;
                const int s = row & (S_ - 1);
                const int b = row >> 11;
                const float* rt = &g_rot[s * 16];
#pragma unroll
                for (int np = 0; np < 2; np++) {
                    const int base = bn + wn * 32 + np * 16;
                    const float vlo0 = acc[mt][2 * np][2 * rr + 0];
                    const float vlo1 = acc[mt][2 * np][2 * rr + 1];
                    const float vhi0 = acc[mt][2 * np + 1][2 * rr + 0];
                    const float vhi1 = acc[mt][2 * np + 1][2 * rr + 1];
                    if (base < 256) {
                        const int h = base >> 4;
                        float a0 = vlo0 + bQv[h * 16 + i];
                        float a1 = vlo1 + bQv[h * 16 + i + 1];
                        float c0 = vhi0 + bQv[h * 16 + i + 8];
                        float c1 = vhi1 + bQv[h * 16 + i + 9];
                        float sn0 = rt[i], sn1 = rt[i + 1];
                        float cs0 = rt[8 + i], cs1 = rt[9 + i];
                        __half* dst = &g_Qh[((size_t)(b * NQK_ + h) * S_ + s) * DQK_];
                        *(__half2*)&dst[i]     = __floats2half2_rn((a0 * cs0 - c0 * sn0) * QSCALE,
                                                                   (a1 * cs1 - c1 * sn1) * QSCALE);
                        *(__half2*)&dst[i + 8] = __floats2half2_rn((c0 * cs0 + a0 * sn0) * QSCALE,
                                                                   (c1 * cs1 + a1 * sn1) * QSCALE);
                    } else if (base < 512) {
                        const int h = (base - 256) >> 4;
                        float a0 = vlo0 + bKv[h * 16 + i];
                        float a1 = vlo1 + bKv[h * 16 + i + 1];
                        float c0 = vhi0 + bKv[h * 16 + i + 8];
                        float c1 = vhi1 + bKv[h * 16 + i + 9];
                        float sn0 = rt[i], sn1 = rt[i + 1];
                        float cs0 = rt[8 + i], cs1 = rt[9 + i];
                        __half* dst = &g_Kh[((size_t)(b * NQK_ + h) * SK_ + s) * DQK_];
                        *(__half2*)&dst[i]     = __floats2half2_rn(a0 * cs0 - c0 * sn0,
                                                                   a1 * cs1 - c1 * sn1);
                        *(__half2*)&dst[i + 8] = __floats2half2_rn(c0 * cs0 + a0 * sn0,
                                                                   c1 * cs1 + a1 * sn1);
                    } else {
                        const int n0 = base - 512;
                        const int h = n0 >> 4;
                        __half* dst = &g_Vh[((size_t)(b * NQK_ + h) * SK_ + s) * DQK_];
                        *(__half2*)&dst[i]     = __floats2half2_rn(vlo0 + bVv[n0 + i],
                                                                   vlo1 + bVv[n0 + i + 1]);
                        *(__half2*)&dst[i + 8] = __floats2half2_rn(vhi0 + bVv[n0 + i + 8],
                                                                   vhi1 + bVv[n0 + i + 9]);
                    }
                }
            }
        }
    }
}

// ---------------------------------------------------------------------------
// 3) Flash attention (exact R11 champion version)
// ---------------------------------------------------------------------------
#define PAD 24

__global__ __launch_bounds__(128, 5)
void attn_mma()
{
    grid_dep_sync();   // PDL: wait for GEMM1's Q/K/V

    const int bh   = blockIdx.y;
    const int pp   = blockIdx.x;          // 0..15
    const int tid  = threadIdx.x;
    const int warp = tid >> 5, lane = tid & 31;

    __shared__ __half Qs[64 * PAD];
    __shared__ __half K0s[16 * PAD];
    __shared__ __half V0s[16 * PAD];
    __shared__ __half Ks[2][128 * PAD];
    __shared__ __half Vs[2][128 * PAD];

    const __half* Kg = g_Kh + (size_t)bh * SK_ * DQK_;
    const __half* Vg = g_Vh + (size_t)bh * SK_ * DQK_;

    const int ld_row = tid >> 1;
    const int ld_off = (tid & 1) * 8;

    if (tid < 32) {
        int pr = tid >> 1, po = (tid & 1) * 8;
        cp16(smem_u32(&K0s[pr * PAD + po]), Kg + (size_t)pr * 16 + po);
        cp16(smem_u32(&V0s[pr * PAD + po]), Vg + (size_t)pr * 16 + po);
    }
    asm volatile("cp.async.commit_group;");

    const int g = lane >> 3, r = lane & 7;
    const int qfrow = warp * 16 + (g & 1) * 8 + r;
    const int qfcol = (g >> 1) * 8;
    const int krow = (g >> 1) * 8 + r;
    const int kcol = (g & 1) * 8;
    const int vrow = (g & 1) * 8 + r;
    const int vcol = (g >> 1) * 8;
    const uint32_t onesb[2] = { 0x3C003C00u, 0x3C003C00u };

#pragma unroll 1
    for (int sel = 0; sel < 2; sel++) {
        const int qt = sel ? pp : (31 - pp);
        const int q0 = qt * 64;
        const __half* Qg = g_Qh + ((size_t)bh * S_ + q0) * DQK_;

        __syncthreads();

        *(float4*)&Qs[ld_row * PAD + ld_off] =
            *(const float4*)&Qg[(size_t)ld_row * 16 + ld_off];

        cp16(smem_u32(&Ks[0][ld_row * PAD + ld_off]),        Kg + (size_t)(16 + ld_row) * 16 + ld_off);
        cp16(smem_u32(&Ks[0][(ld_row + 64) * PAD + ld_off]), Kg + (size_t)(80 + ld_row) * 16 + ld_off);
        cp16(smem_u32(&Vs[0][ld_row * PAD + ld_off]),        Vg + (size_t)(16 + ld_row) * 16 + ld_off);
        cp16(smem_u32(&Vs[0][(ld_row + 64) * PAD + ld_off]), Vg + (size_t)(80 + ld_row) * 16 + ld_off);
        asm volatile("cp.async.commit_group;");

        asm volatile("cp.async.wait_group 1;" ::: "memory");
        __syncthreads();

        uint32_t qa[4];
        ldm4(qa[0], qa[1], qa[2], qa[3], smem_u32(&Qs[qfrow * PAD + qfcol]));

        float m0, m1;
        float o[2][4] = {{0.f,0.f,0.f,0.f},{0.f,0.f,0.f,0.f}};
        float oL[4]   = {0.f,0.f,0.f,0.f};

        // ---- prologue: 16 keys, unmasked ----
        {
            float sc[2][4] = {{0.f,0.f,0.f,0.f},{0.f,0.f,0.f,0.f}};
            uint32_t b0, b1, b2, b3;
            ldm4(b0, b1, b2, b3, smem_u32(&K0s[krow * PAD + kcol]));
            {
                uint32_t bl[2] = { b0, b1 }, bh2[2] = { b2, b3 };
                mma16816(sc[0], qa, bl);
                mma16816(sc[1], qa, bh2);
            }
            float rm0 = fmaxf(fmaxf(sc[0][0], sc[0][1]), fmaxf(sc[1][0], sc[1][1]));
            float rm1 = fmaxf(fmaxf(sc[0][2], sc[0][3]), fmaxf(sc[1][2], sc[1][3]));
            rm0 = fmaxf(rm0, __shfl_xor_sync(0xffffffff, rm0, 1));
            rm0 = fmaxf(rm0, __shfl_xor_sync(0xffffffff, rm0, 2));
            rm1 = fmaxf(rm1, __shfl_xor_sync(0xffffffff, rm1, 1));
            rm1 = fmaxf(rm1, __shfl_xor_sync(0xffffffff, rm1, 2));
            m0 = rm0; m1 = rm1;

            uint32_t pa[4];
            pa[0] = ex2h2(sc[0][0] - m0, sc[0][1] - m0);
            pa[1] = ex2h2(sc[0][2] - m1, sc[0][3] - m1);
            pa[2] = ex2h2(sc[1][0] - m0, sc[1][1] - m0);
            pa[3] = ex2h2(sc[1][2] - m1, sc[1][3] - m1);

            uint32_t v0, v1, v2, v3;
            ldm4t(v0, v1, v2, v3, smem_u32(&V0s[vrow * PAD + vcol]));
            uint32_t bl[2] = { v0, v1 }, bh2[2] = { v2, v3 };
            mma16816(o[0], pa, bl);
            mma16816(o[1], pa, bh2);
            mma16816(oL,   pa, onesb);
        }

        const int jmax = (q0 + 63) >> 7;

        for (int jt = 0; jt <= jmax; jt++) {
            const int buf = jt & 1;
            if (jt < jmax) {
                const size_t kb = (size_t)(16 + (jt + 1) * 128);
                cp16(smem_u32(&Ks[buf ^ 1][ld_row * PAD + ld_off]),        Kg + (kb + ld_row) * 16 + ld_off);
                cp16(smem_u32(&Ks[buf ^ 1][(ld_row + 64) * PAD + ld_off]), Kg + (kb + ld_row + 64) * 16 + ld_off);
                cp16(smem_u32(&Vs[buf ^ 1][ld_row * PAD + ld_off]),        Vg + (kb + ld_row) * 16 + ld_off);
                cp16(smem_u32(&Vs[buf ^ 1][(ld_row + 64) * PAD + ld_off]), Vg + (kb + ld_row + 64) * 16 + ld_off);
                asm volatile("cp.async.commit_group;");
                asm volatile("cp.async.wait_group 1;" ::: "memory");
            } else {
                asm volatile("cp.async.wait_group 0;" ::: "memory");
            }
            __syncthreads();

            if (jt < jmax) {
                // ===== FULL TILE: 128 keys, single softmax update =====
                float sc[16][4];
#pragma unroll
                for (int nt = 0; nt < 16; nt++)
#pragma unroll
                    for (int tt = 0; tt < 4; tt++) sc[nt][tt] = 0.f;

#pragma unroll
                for (int i = 0; i < 8; i++) {
                    uint32_t b0, b1, b2, b3;
                    ldm4(b0, b1, b2, b3,
                         smem_u32(&Ks[buf][(16 * i + krow) * PAD + kcol]));
                    uint32_t bl[2] = { b0, b1 }, bh2[2] = { b2, b3 };
                    mma16816(sc[2 * i],     qa, bl);
                    mma16816(sc[2 * i + 1], qa, bh2);
                }

                float rm0 = sc[0][0], rm1 = sc[0][2];
#pragma unroll
                for (int nt = 0; nt < 16; nt++) {
                    rm0 = fmaxf(rm0, fmaxf(sc[nt][0], sc[nt][1]));
                    rm1 = fmaxf(rm1, fmaxf(sc[nt][2], sc[nt][3]));
                }
                rm0 = fmaxf(rm0, __shfl_xor_sync(0xffffffff, rm0, 1));
                rm0 = fmaxf(rm0, __shfl_xor_sync(0xffffffff, rm0, 2));
                rm1 = fmaxf(rm1, __shfl_xor_sync(0xffffffff, rm1, 1));
                rm1 = fmaxf(rm1, __shfl_xor_sync(0xffffffff, rm1, 2));

                const float mn0 = fmaxf(m0, rm0);
                const float mn1 = fmaxf(m1, rm1);
                const float c0 = ex2f(m0 - mn0);
                const float c1 = ex2f(m1 - mn1);
                m0 = mn0; m1 = mn1;
                o[0][0] *= c0; o[0][1] *= c0; o[0][2] *= c1; o[0][3] *= c1;
                o[1][0] *= c0; o[1][1] *= c0; o[1][2] *= c1; o[1][3] *= c1;
                oL[0]   *= c0; oL[1]   *= c0; oL[2]   *= c1; oL[3]   *= c1;

#pragma unroll
                for (int kt = 0; kt < 8; kt++) {
                    uint32_t pa[4];
                    pa[0] = ex2h2(sc[2 * kt][0] - mn0,     sc[2 * kt][1] - mn0);
                    pa[1] = ex2h2(sc[2 * kt][2] - mn1,     sc[2 * kt][3] - mn1);
                    pa[2] = ex2h2(sc[2 * kt + 1][0] - mn0, sc[2 * kt + 1][1] - mn0);
                    pa[3] = ex2h2(sc[2 * kt + 1][2] - mn1, sc[2 * kt + 1][3] - mn1);
                    uint32_t v0, v1, v2, v3;
                    ldm4t(v0, v1, v2, v3,
                          smem_u32(&Vs[buf][(16 * kt + vrow) * PAD + vcol]));
                    uint32_t bl[2] = { v0, v1 }, bh2[2] = { v2, v3 };
                    mma16816(o[0], pa, bl);
                    mma16816(o[1], pa, bh2);
                    mma16816(oL,   pa, onesb);
                }
                __syncthreads();
            } else {
                // ===== DIAG TILE: chunked + warp-uniform skips + mask =====
                const int off = q0 - 128 * jt;
                const int wb  = off + warp * 16 + 15;

#pragma unroll
                for (int c = 0; c < 2; c++) {
                    if (c * 64 <= wb) {
                        float sc[8][4];
#pragma unroll
                        for (int nt = 0; nt < 8; nt++)
#pragma unroll
                            for (int tt = 0; tt < 4; tt++) sc[nt][tt] = 0.f;

#pragma unroll
                        for (int i = 0; i < 4; i++) {
                            if ((c * 64 + i * 16) <= wb) {
                                uint32_t b0, b1, b2, b3;
                                ldm4(b0, b1, b2, b3,
                                     smem_u32(&Ks[buf][(16 * (c * 4 + i) + krow) * PAD + kcol]));
                                uint32_t bl[2] = { b0, b1 }, bh2[2] = { b2, b3 };
                                mma16816(sc[2 * i],     qa, bl);
                                mma16816(sc[2 * i + 1], qa, bh2);
                            }
                        }

                        {
                            const int jb = c * 64 + (lane & 3) * 2;
                            const int t0 = off + warp * 16 + (lane >> 2);
                            const int t1 = t0 + 8;
#pragma unroll
                            for (int nt = 0; nt < 8; nt++) {
                                int j0 = jb + nt * 8;
                                if (j0     > t0) sc[nt][0] = -1e30f;
                                if (j0 + 1 > t0) sc[nt][1] = -1e30f;
                                if (j0     > t1) sc[nt][2] = -1e30f;
                                if (j0 + 1 > t1) sc[nt][3] = -1e30f;
                            }
                        }

                        float rm0 = sc[0][0], rm1 = sc[0][2];
#pragma unroll
                        for (int nt = 0; nt < 8; nt++) {
                            rm0 = fmaxf(rm0, fmaxf(sc[nt][0], sc[nt][1]));
                            rm1 = fmaxf(rm1, fmaxf(sc[nt][2], sc[nt][3]));
                        }
                        rm0 = fmaxf(rm0, __shfl_xor_sync(0xffffffff, rm0, 1));
                        rm0 = fmaxf(rm0, __shfl_xor_sync(0xffffffff, rm0, 2));
                        rm1 = fmaxf(rm1, __shfl_xor_sync(0xffffffff, rm1, 1));
                        rm1 = fmaxf(rm1, __shfl_xor_sync(0xffffffff, rm1, 2));

                        const float mn0 = fmaxf(m0, rm0);
                        const float mn1 = fmaxf(m1, rm1);
                        const float c0 = ex2f(m0 - mn0);
                        const float c1 = ex2f(m1 - mn1);
                        m0 = mn0; m1 = mn1;
                        o[0][0] *= c0; o[0][1] *= c0; o[0][2] *= c1; o[0][3] *= c1;
                        o[1][0] *= c0; o[1][1] *= c0; o[1][2] *= c1; o[1][3] *= c1;
                        oL[0]   *= c0; oL[1]   *= c0; oL[2]   *= c1; oL[3]   *= c1;

#pragma unroll
                        for (int kt = 0; kt < 4; kt++) {
                            if ((c * 64 + kt * 16) <= wb) {
                                uint32_t pa[4];
                                pa[0] = ex2h2(sc[2 * kt][0] - mn0,     sc[2 * kt][1] - mn0);
                                pa[1] = ex2h2(sc[2 * kt][2] - mn1,     sc[2 * kt][3] - mn1);
                                pa[2] = ex2h2(sc[2 * kt + 1][0] - mn0, sc[2 * kt + 1][1] - mn0);
                                pa[3] = ex2h2(sc[2 * kt + 1][2] - mn1, sc[2 * kt + 1][3] - mn1);
                                uint32_t v0, v1, v2, v3;
                                ldm4t(v0, v1, v2, v3,
                                      smem_u32(&Vs[buf][(16 * (c * 4 + kt) + vrow) * PAD + vcol]));
                                uint32_t bl[2] = { v0, v1 }, bh2[2] = { v2, v3 };
                                mma16816(o[0], pa, bl);
                                mma16816(o[1], pa, bh2);
                                mma16816(oL,   pa, onesb);
                            }
                        }
                    }
                }
                __syncthreads();
            }
        }

        const float inv0 = 1.f / oL[0];
        const float inv1 = 1.f / oL[2];

        const int qrow0 = q0 + warp * 16 + (lane >> 2);
        const int b = bh >> 4, h = bh & 15;
        const int col = (lane & 3) * 2;
#pragma unroll
        for (int vt = 0; vt < 2; vt++) {
            uint32_t lo = packh2(o[vt][0] * inv0, o[vt][1] * inv0);
            uint32_t hi = packh2(o[vt][2] * inv1, o[vt][3] * inv1);
            size_t base0 = ((size_t)(b * S_ + qrow0)     ) * NOV_ + h * 16 + vt * 8 + col;
            size_t base1 = ((size_t)(b * S_ + qrow0 + 8) ) * NOV_ + h * 16 + vt * 8 + col;
            *(uint32_t*)&g_Zh[base0] = lo;
            *(uint32_t*)&g_Zh[base1] = hi;
        }
    }
}

// ---------------------------------------------------------------------------
// Launch (PDL: dependent kernels launch-overlap with producer tails)
// ---------------------------------------------------------------------------
template<typename F, typename... Args>
static void launch_pdl(F func, dim3 grid, dim3 block, size_t smem, Args... args)
{
    cudaLaunchConfig_t cfg = {};
    cfg.gridDim = grid;
    cfg.blockDim = block;
    cfg.dynamicSmemBytes = smem;
    cfg.stream = 0;
    cudaLaunchAttribute attr[1];
    attr[0].id = cudaLaunchAttributeProgrammaticStreamSerialization;
    attr[0].val.programmaticStreamSerializationAllowed = 1;
    cfg.attrs = attr;
    cfg.numAttrs = 1;
    cudaLaunchKernelEx(&cfg, func, args...);
}

extern "C" void kernel_launch(void* const* d_in, const int* in_sizes, int n_in,
                              void* d_out, int out_size)
{
    const float* resid = (const float*)d_in[0];
    const float* W_Q   = (const float*)d_in[1];
    const float* W_K   = (const float*)d_in[2];
    const float* W_V   = (const float*)d_in[3];
    const float* W_O   = (const float*)d_in[4];
    const float* b_Q   = (const float*)d_in[5];
    const float* b_K   = (const float*)d_in[6];
    const float* b_V   = (const float*)d_in[7];
    const float* b_O   = (const float*)d_in[8];
    const float* v_k   = (const float*)d_in[9];
    const float* v_v   = (const float*)d_in[10];
    float* out = (float*)d_out;

    __half *Ah, *Wh1, *Wh2, *Zh;
    cudaGetSymbolAddress((void**)&Ah,  g_Ah);
    cudaGetSymbolAddress((void**)&Wh1, g_Wh1);
    cudaGetSymbolAddress((void**)&Wh2, g_Wh2);
    cudaGetSymbolAddress((void**)&Zh,  g_Zh);

    cudaFuncSetAttribute(hgemm<0>, cudaFuncAttributeMaxDynamicSharedMemorySize, HG_SMEM_BYTES);
    cudaFuncSetAttribute(hgemm<1>, cudaFuncAttributeMaxDynamicSharedMemorySize, HG_SMEM_BYTES);

    // 1) fused prep
    prep_kernel<<<PREP_BLKS, 256>>>(W_Q, W_K, W_V, W_O, resid, v_k, v_v);

    // 2) GEMM1 + fused bias/rotary/scatter epilogue -> g_Qh/g_Kh/g_Vh
    launch_pdl(hgemm<1>, dim3(DM_ / 128, BS_ / 64), dim3(256), (size_t)HG_SMEM_BYTES,
               Ah, (const __half*)Wh1, (float*)nullptr, BS_, DM_, DM_,
               (const float*)nullptr, b_Q, b_K, b_V);

    // 3) tensor-core flash attention
    launch_pdl(attn_mma, dim3(16, B_ * NQK_), dim3(128), (size_t)0);

    // 4) GEMM2: (4096 x 768) = Zh * Wh2^T + b_O -> out fp32
    launch_pdl(hgemm<0>, dim3(DM_ / 128, BS_ / 64), dim3(256), (size_t)HG_SMEM_BYTES,
               (const __half*)Zh, (const __half*)Wh2, out, BS_, DM_, NOV_,
               b_O, (const float*)nullptr, (const float*)nullptr, (const float*)nullptr);
}